// round 2
// baseline (speedup 1.0000x reference)
#include <cuda_runtime.h>
#include <math.h>

#define NMAX 400000
typedef unsigned long long ull;

__device__ int g_cnt_m;
__device__ int g_cnt_u;
__device__ int g_mask_mode;
__device__ int g_idx[NMAX];

// ---------------- packed f32x2 helpers (sm_103a) ----------------
static __device__ __forceinline__ ull pk2(float x){
    ull r; asm("mov.b64 %0, {%1, %1};" : "=l"(r) : "f"(x)); return r;
}
static __device__ __forceinline__ void ffma2(ull &d, ull a, ull b){
    asm("fma.rn.f32x2 %0, %1, %2, %0;" : "+l"(d) : "l"(a), "l"(b));
}
static __device__ __forceinline__ float2 unpk(ull v){
    float2 f; asm("mov.b64 {%0, %1}, %2;" : "=f"(f.x), "=f"(f.y) : "l"(v)); return f;
}
static __device__ __forceinline__ float sigm(float x){ return 1.0f/(1.0f+expf(-x)); }

// ---------------- setup: mask dtype sniff + counter reset ----------------
__global__ void setup_kernel(const unsigned char* __restrict__ mb){
    __shared__ int s3f, s3f1, s1off;
    if (threadIdx.x == 0){ s3f = 0; s3f1 = 0; s1off = 0; }
    __syncthreads();
    int a = 0, b = 0, c = 0;
    for (int i = threadIdx.x; i < 4096; i += blockDim.x){
        unsigned v = mb[i];
        if (v == 0x3fu){ a = 1; if ((i & 3) == 1) b = 1; }
        if (v == 0x01u && (i & 3) != 0) c = 1;
    }
    if (a) atomicOr(&s3f, 1);
    if (b) atomicOr(&s3f1, 1);
    if (c) atomicOr(&s1off, 1);
    __syncthreads();
    if (threadIdx.x == 0){
        int mode;
        if (s3f) mode = s3f1 ? 3 : 2;     // 3=bf16, 2=f32
        else     mode = s1off ? 0 : 1;    // 0=u8, 1=i32
        g_mask_mode = mode;
        g_cnt_m = 0;
        g_cnt_u = 0;
    }
}

static __device__ __forceinline__ bool read_mask(const void* m, int i, int mode){
    if (mode == 0) return ((const unsigned char*)m)[i] != 0;
    if (mode == 1) return ((const int*)m)[i] != 0;
    if (mode == 2) return ((const float*)m)[i] != 0.0f;
    return ((const unsigned short*)m)[i] != 0;
}

// ---------------- elementwise: opacity, passthroughs, mask partition ----------------
__global__ void elem_kernel(const float* __restrict__ rot_emb, const float* __restrict__ shs_emb,
                            const float* __restrict__ tim, const float* __restrict__ h_emb,
                            const void* __restrict__ mask, float* __restrict__ out, int n){
    int i = blockIdx.x*blockDim.x + threadIdx.x;
    if (i >= n) return;
    int mode = g_mask_mode;
    float t0 = tim[0];
    bool msk = read_mask(mask, i, mode);
    float he0 = h_emb[3*i], he1 = h_emb[3*i+1], he2 = h_emb[3*i+2];
    float op;
    if (msk){
        float mu = sigm(he2);
        float w  = he1*he1;
        float d  = t0 - mu;
        op = expf(-w*d*d);
    } else {
        op = sigm(he0);
    }
    out[(size_t)7*n + i] = op;
    if (msk){
        int p = atomicAdd(&g_cnt_m, 1);
        g_idx[p] = i;
    } else {
        int p = atomicAdd(&g_cnt_u, 1);
        g_idx[n-1-p] = i;
        // rot passthrough
        ((float4*)(out + (size_t)3*n))[i] = ((const float4*)rot_emb)[i];
        // shs passthrough
        const float4* s4 = (const float4*)shs_emb + (size_t)i*12;
        float4* d4 = (float4*)(out + (size_t)8*n) + (size_t)i*12;
        #pragma unroll
        for (int q = 0; q < 12; q++) d4[q] = s4[q];
    }
}

// ---------------- smem layout (floats) ----------------
// A : 0      .. 16704   (64 x 261) activations (h after stem)
// B : 16704  .. 33408   (64 x 261) feat, then h1 per head
// W : 33408  .. 49792   weight staging (64 rows x 64 float4, swizzled) / small w2
#define SMEM_FLOATS 49792
#define SMEM_BYTES  (SMEM_FLOATS*4)

// ---------------- fused GEMM + bias + relu : s_out = relu(s_in @ gw + gb) ----------------
// s_in: 64 x K (stride 261), gw: K x 256 row-major, s_out: 64 x 256 (stride 261)
static __device__ __forceinline__ void gemm_relu(
    const float* __restrict__ gw, const float* __restrict__ gb,
    const float* __restrict__ s_in, float* __restrict__ s_out,
    float* smbase, int kchunks)
{
    float4* wt4 = (float4*)(smbase + 33408);
    const int t = threadIdx.x;
    const int r = t >> 4;        // 16 row-groups of 4 pts
    const int c = t & 15;        // 16 col-groups of 16 cols
    const int sw = (c >> 1) & 7; // swizzle for this thread's 4 float4 slots

    ull acc[4][8];
    #pragma unroll
    for (int i = 0; i < 4; i++)
        #pragma unroll
        for (int p = 0; p < 8; p++) acc[i][p] = 0ull;

    for (int kc = 0; kc < kchunks; kc++){
        __syncthreads();
        // stage 64 x 256 weight chunk, swizzled by float4 slot
        #pragma unroll
        for (int j = 0; j < 16; j++){
            int idx = j*256 + t;
            int row = idx >> 6, slot = idx & 63;
            float4 v = *(const float4*)(gw + (size_t)((kc<<6)+row)*256 + (slot<<2));
            wt4[(row<<6) + (slot ^ ((slot>>3)&7))] = v;
        }
        __syncthreads();
        const float* a0 = s_in + (r<<2)*261 + (kc<<6);
        #pragma unroll 2
        for (int k = 0; k < 64; k++){
            ull pa0 = pk2(a0[k]);
            ull pa1 = pk2(a0[261+k]);
            ull pa2 = pk2(a0[2*261+k]);
            ull pa3 = pk2(a0[3*261+k]);
            const float4* wr = wt4 + (k<<6);
            #pragma unroll
            for (int j = 0; j < 4; j++){
                union { float4 f; ull u[2]; } bu;
                bu.f = wr[((c<<2)+j) ^ sw];
                ffma2(acc[0][2*j],   pa0, bu.u[0]); ffma2(acc[0][2*j+1], pa0, bu.u[1]);
                ffma2(acc[1][2*j],   pa1, bu.u[0]); ffma2(acc[1][2*j+1], pa1, bu.u[1]);
                ffma2(acc[2][2*j],   pa2, bu.u[0]); ffma2(acc[2][2*j+1], pa2, bu.u[1]);
                ffma2(acc[3][2*j],   pa3, bu.u[0]); ffma2(acc[3][2*j+1], pa3, bu.u[1]);
            }
        }
    }
    // epilogue: bias + relu -> s_out
    #pragma unroll
    for (int i = 0; i < 4; i++){
        float* orow = s_out + ((r<<2)+i)*261 + (c<<4);
        #pragma unroll
        for (int p = 0; p < 8; p++){
            float2 f = unpk(acc[i][p]);
            int col = (c<<4) + 2*p;
            orow[2*p]   = fmaxf(f.x + gb[col],   0.0f);
            orow[2*p+1] = fmaxf(f.y + gb[col+1], 0.0f);
        }
    }
}

// ---------------- phase A: K-planes bilinear sampling -> feat (64 x 64 into Bm) ----------------
static __device__ __forceinline__ void phaseA(
    const float* __restrict__ sp, const float* __restrict__ tp,
    const float* __restrict__ rays, const float* __restrict__ tim,
    const int* sidx, float* __restrict__ Bm)
{
    const int t = threadIdx.x;
    const int pt = t >> 2, fg = t & 3;
    const int gi = sidx[pt];
    float px = rays[3*gi], py = rays[3*gi+1], pz = rays[3*gi+2];
    float tv = tim[gi];
    float cx = fminf(fmaxf((px*(1.0f/1.3f) + 1.0f)*0.5f, 0.0f), 1.0f) * 127.0f;
    float cy = fminf(fmaxf((py*(1.0f/1.3f) + 1.0f)*0.5f, 0.0f), 1.0f) * 127.0f;
    float cz = fminf(fmaxf((pz*(1.0f/1.3f) + 1.0f)*0.5f, 0.0f), 1.0f) * 127.0f;
    float tq = fminf(fmaxf(tv, 0.0f), 1.0f) * 63.0f;

    const float* PB[6];
    int O00[6], O10[6], O01[6], O11[6];
    float W00[6], W10[6], W01[6], W11[6];

#define SETP(s, bp, R2, uu, vv) { \
    float u_ = fminf(fmaxf((uu), 0.0f), 127.0f); \
    float v_ = fminf(fmaxf((vv), 0.0f), (float)((R2)-1)); \
    int i0 = (int)u_; int j0 = (int)v_; \
    int i1 = min(i0+1, 127); int j1 = min(j0+1, (R2)-1); \
    float fu = u_ - (float)i0, fv = v_ - (float)j0; \
    PB[s] = (bp); \
    O00[s] = (i0*(R2)+j0)*64; O10[s] = (i1*(R2)+j0)*64; \
    O01[s] = (i0*(R2)+j1)*64; O11[s] = (i1*(R2)+j1)*64; \
    W00[s] = (1.0f-fu)*(1.0f-fv); W10[s] = fu*(1.0f-fv); \
    W01[s] = (1.0f-fu)*fv;        W11[s] = fu*fv; }

    SETP(0, sp,           128, cx, cy)
    SETP(1, sp + 1048576, 128, cx, cz)
    SETP(2, sp + 2097152, 128, cy, cz)
    SETP(3, tp,            64, cx, tq)
    SETP(4, tp + 524288,   64, cy, tq)
    SETP(5, tp + 1048576,  64, cz, tq)
#undef SETP

    #pragma unroll
    for (int q = 0; q < 4; q++){
        int f = fg*16 + q*4;
        float r0 = 1.0f, r1 = 1.0f, r2 = 1.0f, r3 = 1.0f;
        #pragma unroll
        for (int s = 0; s < 6; s++){
            const float* b = PB[s] + f;
            float4 v00 = *(const float4*)(b + O00[s]);
            float4 v10 = *(const float4*)(b + O10[s]);
            float4 v01 = *(const float4*)(b + O01[s]);
            float4 v11 = *(const float4*)(b + O11[s]);
            float sx = v00.x*W00[s] + v10.x*W10[s] + v01.x*W01[s] + v11.x*W11[s];
            float sy = v00.y*W00[s] + v10.y*W10[s] + v01.y*W01[s] + v11.y*W11[s];
            float sz = v00.z*W00[s] + v10.z*W10[s] + v01.z*W01[s] + v11.z*W11[s];
            float sw_ = v00.w*W00[s] + v10.w*W10[s] + v01.w*W01[s] + v11.w*W11[s];
            r0 *= sx; r1 *= sy; r2 *= sz; r3 *= sw_;
        }
        float* dst = Bm + pt*261 + f;
        dst[0] = r0; dst[1] = r1; dst[2] = r2; dst[3] = r3;
    }
}

// ---------------- small head: out = residual + h1 @ w2 + b2 ----------------
static __device__ __forceinline__ void head3(
    const float* __restrict__ Bm, const float* __restrict__ ws, const float* __restrict__ b2,
    const float* __restrict__ rays, float* __restrict__ out, const int* sidx)
{
    const int t = threadIdx.x;
    if (t < 192){
        int pt = t/3, col = t - pt*3;
        float acc = b2[col];
        const float* h = Bm + pt*261;
        #pragma unroll 8
        for (int k = 0; k < 256; k++) acc += h[k]*ws[k*3 + col];
        int gi = sidx[pt];
        out[(size_t)gi*3 + col] = rays[gi*3 + col] + acc;
    }
}

__global__ void __launch_bounds__(256, 1) main_kernel(
    const float* __restrict__ rays, const float* __restrict__ rot_emb,
    const float* __restrict__ shs_emb, const float* __restrict__ tim,
    const float* __restrict__ tgt_sp, const float* __restrict__ tgt_tp,
    const float* __restrict__ bg_sp,  const float* __restrict__ bg_tp,
    const float* __restrict__ st_w,   const float* __restrict__ st_b,
    const float* __restrict__ bg_st_w, const float* __restrict__ bg_st_b,
    const float* __restrict__ pos_w1, const float* __restrict__ pos_b1,
    const float* __restrict__ pos_w2, const float* __restrict__ pos_b2,
    const float* __restrict__ bgpos_w1, const float* __restrict__ bgpos_b1,
    const float* __restrict__ bgpos_w2, const float* __restrict__ bgpos_b2,
    const float* __restrict__ rot_w1, const float* __restrict__ rot_b1,
    const float* __restrict__ rot_w2, const float* __restrict__ rot_b2,
    const float* __restrict__ shs_w1, const float* __restrict__ shs_b1,
    const float* __restrict__ shs_w2, const float* __restrict__ shs_b2,
    float* __restrict__ out, int n)
{
    extern __shared__ float sm[];
    float* A  = sm;
    float* Bm = sm + 16704;
    float* ws = sm + 33408;
    __shared__ int sidx[64];
    __shared__ int s_meta[3];

    const int t = threadIdx.x;
    if (t == 0){
        int mc = g_cnt_m;
        int mb = (mc + 63) >> 6;
        int bid = blockIdx.x;
        int seg, start, cnt;
        if (bid < mb){ seg = 0; start = bid << 6; cnt = min(64, mc - start); }
        else {
            int uc = n - mc;
            start = (bid - mb) << 6;
            seg = 1;
            cnt = (start < uc) ? min(64, uc - start) : 0;
        }
        s_meta[0] = seg; s_meta[1] = cnt; s_meta[2] = start;
    }
    __syncthreads();
    const int cnt = s_meta[1];
    if (cnt <= 0) return;
    const int seg = s_meta[0], start = s_meta[2];
    if (t < 64){
        int j = (t < cnt) ? t : 0;
        sidx[t] = (seg == 0) ? g_idx[start + j] : g_idx[n - 1 - (start + j)];
    }
    __syncthreads();

    // feat -> Bm
    phaseA(seg ? bg_sp : tgt_sp, seg ? bg_tp : tgt_tp, rays, tim, sidx, Bm);
    __syncthreads();

    // stem: h = relu(feat @ st_w + st_b) -> A
    gemm_relu(seg ? bg_st_w : st_w, seg ? bg_st_b : st_b, Bm, A, sm, 1);
    __syncthreads();

    if (seg == 0){
        const float* w1s[3] = {pos_w1, rot_w1, shs_w1};
        const float* b1s[3] = {pos_b1, rot_b1, shs_b1};
        const float* w2s[3] = {pos_w2, rot_w2, shs_w2};
        const float* b2s[3] = {pos_b2, rot_b2, shs_b2};
        const int    wn [3] = {768, 1024, 12288};
        #pragma unroll 1
        for (int h = 0; h < 3; h++){
            gemm_relu(w1s[h], b1s[h], A, Bm, sm, 4);
            __syncthreads();
            for (int i = t; i < wn[h]; i += 256) ws[i] = w2s[h][i];
            __syncthreads();
            if (h == 0){
                head3(Bm, ws, b2s[0], rays, out, sidx);
            } else if (h == 1){
                // rot head: 4 cols
                int pt = t >> 2, col = t & 3;
                float acc = b2s[1][col];
                const float* hh = Bm + pt*261;
                #pragma unroll 8
                for (int k = 0; k < 256; k++) acc += hh[k]*ws[k*4 + col];
                int gi = sidx[pt];
                out[(size_t)3*n + (size_t)gi*4 + col] = rot_emb[gi*4 + col] + acc;
            } else {
                // shs head: 48 cols, each thread does 12
                int pt = t & 63, cg = t >> 6;
                int c0 = cg*12;
                float acc[12];
                #pragma unroll
                for (int j = 0; j < 12; j++) acc[j] = b2s[2][c0 + j];
                const float* hh = Bm + pt*261;
                #pragma unroll 4
                for (int k = 0; k < 256; k++){
                    float a = hh[k];
                    const float4* w4 = (const float4*)(ws + k*48 + c0);
                    float4 bv0 = w4[0], bv1 = w4[1], bv2 = w4[2];
                    acc[0]  += a*bv0.x; acc[1]  += a*bv0.y; acc[2]  += a*bv0.z; acc[3]  += a*bv0.w;
                    acc[4]  += a*bv1.x; acc[5]  += a*bv1.y; acc[6]  += a*bv1.z; acc[7]  += a*bv1.w;
                    acc[8]  += a*bv2.x; acc[9]  += a*bv2.y; acc[10] += a*bv2.z; acc[11] += a*bv2.w;
                }
                int gi = sidx[pt];
                const float* se = shs_emb + (size_t)gi*48 + c0;
                float* od = out + (size_t)8*n + (size_t)gi*48 + c0;
                #pragma unroll
                for (int j = 0; j < 12; j++) od[j] = se[j] + acc[j];
            }
            __syncthreads();
        }
    } else {
        gemm_relu(bgpos_w1, bgpos_b1, A, Bm, sm, 4);
        __syncthreads();
        for (int i = t; i < 768; i += 256) ws[i] = bgpos_w2[i];
        __syncthreads();
        head3(Bm, ws, bgpos_b2, rays, out, sidx);
    }
}

extern "C" void kernel_launch(void* const* d_in, const int* in_sizes, int n_in,
                              void* d_out, int out_size) {
    const float* rays    = (const float*)d_in[0];
    const float* rot_emb = (const float*)d_in[1];
    const float* shs_emb = (const float*)d_in[3];
    const float* tim     = (const float*)d_in[5];
    const float* h_emb   = (const float*)d_in[6];
    const void*  mask    = d_in[7];
    const float* tgt_sp  = (const float*)d_in[8];
    const float* tgt_tp  = (const float*)d_in[9];
    const float* bg_sp   = (const float*)d_in[10];
    const float* bg_tp   = (const float*)d_in[11];
    const float* st_w    = (const float*)d_in[12];
    const float* st_b    = (const float*)d_in[13];
    const float* bg_st_w = (const float*)d_in[14];
    const float* bg_st_b = (const float*)d_in[15];
    const float* pos_w1  = (const float*)d_in[16];
    const float* pos_b1  = (const float*)d_in[17];
    const float* pos_w2  = (const float*)d_in[18];
    const float* pos_b2  = (const float*)d_in[19];
    const float* bgpos_w1= (const float*)d_in[20];
    const float* bgpos_b1= (const float*)d_in[21];
    const float* bgpos_w2= (const float*)d_in[22];
    const float* bgpos_b2= (const float*)d_in[23];
    const float* rot_w1  = (const float*)d_in[24];
    const float* rot_b1  = (const float*)d_in[25];
    const float* rot_w2  = (const float*)d_in[26];
    const float* rot_b2  = (const float*)d_in[27];
    const float* shs_w1  = (const float*)d_in[28];
    const float* shs_b1  = (const float*)d_in[29];
    const float* shs_w2  = (const float*)d_in[30];
    const float* shs_b2  = (const float*)d_in[31];
    float* out = (float*)d_out;
    int n = in_sizes[0] / 3;

    cudaFuncSetAttribute(main_kernel, cudaFuncAttributeMaxDynamicSharedMemorySize, SMEM_BYTES);

    setup_kernel<<<1, 256>>>((const unsigned char*)mask);
    elem_kernel<<<(n + 255)/256, 256>>>(rot_emb, shs_emb, tim, h_emb, mask, out, n);
    int nb = (n + 63)/64 + 1;
    main_kernel<<<nb, 256, SMEM_BYTES>>>(
        rays, rot_emb, shs_emb, tim,
        tgt_sp, tgt_tp, bg_sp, bg_tp,
        st_w, st_b, bg_st_w, bg_st_b,
        pos_w1, pos_b1, pos_w2, pos_b2,
        bgpos_w1, bgpos_b1, bgpos_w2, bgpos_b2,
        rot_w1, rot_b1, rot_w2, rot_b2,
        shs_w1, shs_b1, shs_w2, shs_b2,
        out, n);
}

// round 3
// speedup vs baseline: 1.0924x; 1.0924x over previous
#include <cuda_runtime.h>
#include <math.h>

#define NMAX 400000
typedef unsigned long long ull;
typedef unsigned int uint32;

__device__ int g_cnt_m;
__device__ int g_cnt_u;
__device__ int g_mask_mode;
__device__ int g_idx[NMAX];

static __device__ __forceinline__ float sigm(float x){ return 1.0f/(1.0f+expf(-x)); }
static __device__ __forceinline__ float to_tf32(float x){
    float r; asm("cvt.rna.tf32.f32 %0, %1;" : "=f"(r) : "f"(x)); return r;
}
static __device__ __forceinline__ void mma8(float* d, uint32 a0, uint32 a1, uint32 a2, uint32 a3,
                                            uint32 b0, uint32 b1){
    asm volatile(
      "mma.sync.aligned.m16n8k8.row.col.f32.tf32.tf32.f32 "
      "{%0,%1,%2,%3},{%4,%5,%6,%7},{%8,%9},{%0,%1,%2,%3};"
      : "+f"(d[0]), "+f"(d[1]), "+f"(d[2]), "+f"(d[3])
      : "r"(a0), "r"(a1), "r"(a2), "r"(a3), "r"(b0), "r"(b1));
}

// swizzled activation/weight layout:
// logical (row,k) -> float index: row*stride + 2*(u ^ (row&31)) + e
// u = (k>>3)*4 + (k&3), e = (k>>2)&1.  Pair (k0+t, k0+t+4) is one aligned LDS.64.
static __device__ __forceinline__ int sw_idx(int row, int k, int stride){
    int u = ((k >> 3) << 2) + (k & 3);
    int e = (k >> 2) & 1;
    return row*stride + (((u << 1) ^ ((row & 31) << 1))) + e;
}

// ---------------- setup: mask dtype sniff + counter reset ----------------
__global__ void setup_kernel(const unsigned char* __restrict__ mb){
    __shared__ int s3f, s3f1, s1off;
    if (threadIdx.x == 0){ s3f = 0; s3f1 = 0; s1off = 0; }
    __syncthreads();
    int a = 0, b = 0, c = 0;
    for (int i = threadIdx.x; i < 4096; i += blockDim.x){
        unsigned v = mb[i];
        if (v == 0x3fu){ a = 1; if ((i & 3) == 1) b = 1; }
        if (v == 0x01u && (i & 3) != 0) c = 1;
    }
    if (a) atomicOr(&s3f, 1);
    if (b) atomicOr(&s3f1, 1);
    if (c) atomicOr(&s1off, 1);
    __syncthreads();
    if (threadIdx.x == 0){
        int mode;
        if (s3f) mode = s3f1 ? 3 : 2;     // 3=bf16, 2=f32
        else     mode = s1off ? 0 : 1;    // 0=u8, 1=i32
        g_mask_mode = mode;
        g_cnt_m = 0;
        g_cnt_u = 0;
    }
}

static __device__ __forceinline__ bool read_mask(const void* m, int i, int mode){
    if (mode == 0) return ((const unsigned char*)m)[i] != 0;
    if (mode == 1) return ((const int*)m)[i] != 0;
    if (mode == 2) return ((const float*)m)[i] != 0.0f;
    return ((const unsigned short*)m)[i] != 0;
}

// ---------------- elementwise: opacity, passthroughs, mask partition ----------------
__global__ void elem_kernel(const float* __restrict__ rot_emb, const float* __restrict__ shs_emb,
                            const float* __restrict__ tim, const float* __restrict__ h_emb,
                            const void* __restrict__ mask, float* __restrict__ out, int n){
    int i = blockIdx.x*blockDim.x + threadIdx.x;
    if (i >= n) return;
    int mode = g_mask_mode;
    float t0 = tim[0];
    bool msk = read_mask(mask, i, mode);
    float he0 = h_emb[3*i], he1 = h_emb[3*i+1], he2 = h_emb[3*i+2];
    float op;
    if (msk){
        float mu = sigm(he2);
        float w  = he1*he1;
        float d  = t0 - mu;
        op = expf(-w*d*d);
    } else {
        op = sigm(he0);
    }
    out[(size_t)7*n + i] = op;
    if (msk){
        int p = atomicAdd(&g_cnt_m, 1);
        g_idx[p] = i;
    } else {
        int p = atomicAdd(&g_cnt_u, 1);
        g_idx[n-1-p] = i;
        ((float4*)(out + (size_t)3*n))[i] = ((const float4*)rot_emb)[i];
        const float4* s4 = (const float4*)shs_emb + (size_t)i*12;
        float4* d4 = (float4*)(out + (size_t)8*n) + (size_t)i*12;
        #pragma unroll
        for (int q = 0; q < 12; q++) d4[q] = s4[q];
    }
}

// ---------------- smem layout (floats) ----------------
#define SA_OFF    0          // h activations, 64 x 256 swizzled (stride 256)
#define SB_OFF    16384      // weight chunk, 256 n-rows x 64 k swizzled (stride 64) / w2 staging
#define SF_OFF    32768      // feat, 64 x 64 swizzled (stride 64)
#define SH1_OFF   36864      // h1 plain, 64 x 257
#define SBIAS_OFF 53312      // 256 bias
#define SMEM_FLOATS 53568
#define SMEM_BYTES  (SMEM_FLOATS*4)

// ---------------- tf32 tensor-core GEMM: acc[2][8][4] += sIn(64 x K) @ gw(K x 256) ----------------
static __device__ __forceinline__ void mma_gemm(
    float acc[2][8][4],
    const float* __restrict__ gw, const float* __restrict__ gb,
    const float* __restrict__ sIn, int strideA, int kchunks,
    float* __restrict__ sB, float* __restrict__ sBias)
{
    const int t = threadIdx.x;
    const int lane = t & 31, w = t >> 5;
    const int g = lane >> 2, tig = lane & 3;
    const int mb = (w >> 2) * 32, nb = (w & 3) * 64;

    #pragma unroll
    for (int mt = 0; mt < 2; mt++)
        #pragma unroll
        for (int nt = 0; nt < 8; nt++)
            #pragma unroll
            for (int i = 0; i < 4; i++) acc[mt][nt][i] = 0.0f;

    int ra[4], rx2[4];
    #pragma unroll
    for (int mt = 0; mt < 2; mt++)
        #pragma unroll
        for (int h = 0; h < 2; h++){
            int r = mb + mt*16 + g + 8*h;
            ra[mt*2+h]  = r * strideA;
            rx2[mt*2+h] = (r & 31) << 1;
        }
    int bbase[8], bx2[8];
    #pragma unroll
    for (int nt = 0; nt < 8; nt++){
        int nn = nb + nt*8 + g;
        bbase[nt] = nn << 6;
        bx2[nt]   = (nn & 31) << 1;
    }

    const int n4   = (t & 63) * 4;
    const int kb16 = (t >> 6) * 16;

    for (int c = 0; c < kchunks; c++){
        __syncthreads();
        if (c == 0) sBias[t] = gb[t];
        // stage 64 x 256 weight chunk (transposed + swizzled + tf32)
        const float* wp = gw + (size_t)(c*64 + kb16)*256 + n4;
        #pragma unroll 4
        for (int j = 0; j < 16; j++){
            float4 v = *(const float4*)(wp + (size_t)j*256);
            int kl = kb16 + j;
            int u2 = (((kl >> 3) << 2) + (kl & 3)) << 1;
            int e  = (kl >> 2) & 1;
            float vv[4] = {v.x, v.y, v.z, v.w};
            #pragma unroll
            for (int q = 0; q < 4; q++){
                int nn = n4 + q;
                sB[(nn << 6) + (u2 ^ ((nn & 31) << 1)) + e] = to_tf32(vv[q]);
            }
        }
        __syncthreads();
        #pragma unroll
        for (int ls = 0; ls < 8; ls++){
            int q2a = (((c*8 + ls)*4 + tig)) << 1;
            int q2b = ((ls*4 + tig)) << 1;
            uint2 Af[4];
            #pragma unroll
            for (int i = 0; i < 4; i++)
                Af[i] = *(const uint2*)(sIn + ra[i] + (q2a ^ rx2[i]));
            uint2 Bf[8];
            #pragma unroll
            for (int nt = 0; nt < 8; nt++)
                Bf[nt] = *(const uint2*)(sB + bbase[nt] + (q2b ^ bx2[nt]));
            #pragma unroll
            for (int mt = 0; mt < 2; mt++)
                #pragma unroll
                for (int nt = 0; nt < 8; nt++)
                    mma8(acc[mt][nt], Af[2*mt].x, Af[2*mt+1].x, Af[2*mt].y, Af[2*mt+1].y,
                         Bf[nt].x, Bf[nt].y);
        }
    }
}

// epilogue: acc -> swizzled sA (relu + tf32)  [for feeding the next GEMM]
static __device__ __forceinline__ void epi_to_sA(
    float acc[2][8][4], const float* __restrict__ sBias, float* __restrict__ sA)
{
    const int t = threadIdx.x;
    const int lane = t & 31, w = t >> 5;
    const int g = lane >> 2, tig = lane & 3;
    const int mb = (w >> 2) * 32, nb = (w & 3) * 64;
    #pragma unroll
    for (int mt = 0; mt < 2; mt++){
        int r0 = mb + mt*16 + g, r1 = r0 + 8;
        #pragma unroll
        for (int nt = 0; nt < 8; nt++){
            int c0 = nb + nt*8 + 2*tig;
            float b0 = sBias[c0], b1 = sBias[c0+1];
            sA[sw_idx(r0, c0,   256)] = to_tf32(fmaxf(acc[mt][nt][0] + b0, 0.0f));
            sA[sw_idx(r0, c0+1, 256)] = to_tf32(fmaxf(acc[mt][nt][1] + b1, 0.0f));
            sA[sw_idx(r1, c0,   256)] = to_tf32(fmaxf(acc[mt][nt][2] + b0, 0.0f));
            sA[sw_idx(r1, c0+1, 256)] = to_tf32(fmaxf(acc[mt][nt][3] + b1, 0.0f));
        }
    }
}

// epilogue: acc -> plain sH1 (relu, stride 257)  [for scalar w2 heads]
static __device__ __forceinline__ void epi_to_h1(
    float acc[2][8][4], const float* __restrict__ sBias, float* __restrict__ sH1)
{
    const int t = threadIdx.x;
    const int lane = t & 31, w = t >> 5;
    const int g = lane >> 2, tig = lane & 3;
    const int mb = (w >> 2) * 32, nb = (w & 3) * 64;
    #pragma unroll
    for (int mt = 0; mt < 2; mt++){
        int r0 = mb + mt*16 + g, r1 = r0 + 8;
        #pragma unroll
        for (int nt = 0; nt < 8; nt++){
            int c0 = nb + nt*8 + 2*tig;
            float b0 = sBias[c0], b1 = sBias[c0+1];
            sH1[r0*257 + c0]   = fmaxf(acc[mt][nt][0] + b0, 0.0f);
            sH1[r0*257 + c0+1] = fmaxf(acc[mt][nt][1] + b1, 0.0f);
            sH1[r1*257 + c0]   = fmaxf(acc[mt][nt][2] + b0, 0.0f);
            sH1[r1*257 + c0+1] = fmaxf(acc[mt][nt][3] + b1, 0.0f);
        }
    }
}

// ---------------- phase A: K-planes bilinear sampling -> swizzled feat ----------------
static __device__ __forceinline__ void phaseA(
    const float* __restrict__ sp, const float* __restrict__ tp,
    const float* __restrict__ rays, const float* __restrict__ tim,
    const int* sidx, float* __restrict__ sF)
{
    const int t = threadIdx.x;
    const int pt = t >> 2, fg = t & 3;
    const int gi = sidx[pt];
    float px = rays[3*gi], py = rays[3*gi+1], pz = rays[3*gi+2];
    float tv = tim[gi];
    float cx = fminf(fmaxf((px*(1.0f/1.3f) + 1.0f)*0.5f, 0.0f), 1.0f) * 127.0f;
    float cy = fminf(fmaxf((py*(1.0f/1.3f) + 1.0f)*0.5f, 0.0f), 1.0f) * 127.0f;
    float cz = fminf(fmaxf((pz*(1.0f/1.3f) + 1.0f)*0.5f, 0.0f), 1.0f) * 127.0f;
    float tq = fminf(fmaxf(tv, 0.0f), 1.0f) * 63.0f;

    const float* PB[6];
    int O00[6], O10[6], O01[6], O11[6];
    float W00[6], W10[6], W01[6], W11[6];

#define SETP(s, bp, R2, uu, vv) { \
    float u_ = fminf(fmaxf((uu), 0.0f), 127.0f); \
    float v_ = fminf(fmaxf((vv), 0.0f), (float)((R2)-1)); \
    int i0 = (int)u_; int j0 = (int)v_; \
    int i1 = min(i0+1, 127); int j1 = min(j0+1, (R2)-1); \
    float fu = u_ - (float)i0, fv = v_ - (float)j0; \
    PB[s] = (bp); \
    O00[s] = (i0*(R2)+j0)*64; O10[s] = (i1*(R2)+j0)*64; \
    O01[s] = (i0*(R2)+j1)*64; O11[s] = (i1*(R2)+j1)*64; \
    W00[s] = (1.0f-fu)*(1.0f-fv); W10[s] = fu*(1.0f-fv); \
    W01[s] = (1.0f-fu)*fv;        W11[s] = fu*fv; }

    SETP(0, sp,           128, cx, cy)
    SETP(1, sp + 1048576, 128, cx, cz)
    SETP(2, sp + 2097152, 128, cy, cz)
    SETP(3, tp,            64, cx, tq)
    SETP(4, tp + 524288,   64, cy, tq)
    SETP(5, tp + 1048576,  64, cz, tq)
#undef SETP

    #pragma unroll
    for (int q = 0; q < 4; q++){
        int f = fg*16 + q*4;
        float r0 = 1.0f, r1 = 1.0f, r2 = 1.0f, r3 = 1.0f;
        #pragma unroll
        for (int s = 0; s < 6; s++){
            const float* b = PB[s] + f;
            float4 v00 = *(const float4*)(b + O00[s]);
            float4 v10 = *(const float4*)(b + O10[s]);
            float4 v01 = *(const float4*)(b + O01[s]);
            float4 v11 = *(const float4*)(b + O11[s]);
            float sx = v00.x*W00[s] + v10.x*W10[s] + v01.x*W01[s] + v11.x*W11[s];
            float sy = v00.y*W00[s] + v10.y*W10[s] + v01.y*W01[s] + v11.y*W11[s];
            float sz = v00.z*W00[s] + v10.z*W10[s] + v01.z*W01[s] + v11.z*W11[s];
            float sw_ = v00.w*W00[s] + v10.w*W10[s] + v01.w*W01[s] + v11.w*W11[s];
            r0 *= sx; r1 *= sy; r2 *= sz; r3 *= sw_;
        }
        sF[sw_idx(pt, f,   64)] = to_tf32(r0);
        sF[sw_idx(pt, f+1, 64)] = to_tf32(r1);
        sF[sw_idx(pt, f+2, 64)] = to_tf32(r2);
        sF[sw_idx(pt, f+3, 64)] = to_tf32(r3);
    }
}

// ---------------- small head: out = rays + h1 @ w2 + b2 (3 cols) ----------------
static __device__ __forceinline__ void head3(
    const float* __restrict__ sH1, const float* __restrict__ ws, const float* __restrict__ b2,
    const float* __restrict__ rays, float* __restrict__ out, const int* sidx)
{
    const int t = threadIdx.x;
    if (t < 192){
        int pt = t/3, col = t - pt*3;
        float acc = b2[col];
        const float* h = sH1 + pt*257;
        #pragma unroll 8
        for (int k = 0; k < 256; k++) acc += h[k]*ws[k*3 + col];
        int gi = sidx[pt];
        out[(size_t)gi*3 + col] = rays[gi*3 + col] + acc;
    }
}

__global__ void __launch_bounds__(256, 1) main_kernel(
    const float* __restrict__ rays, const float* __restrict__ rot_emb,
    const float* __restrict__ shs_emb, const float* __restrict__ tim,
    const float* __restrict__ tgt_sp, const float* __restrict__ tgt_tp,
    const float* __restrict__ bg_sp,  const float* __restrict__ bg_tp,
    const float* __restrict__ st_w,   const float* __restrict__ st_b,
    const float* __restrict__ bg_st_w, const float* __restrict__ bg_st_b,
    const float* __restrict__ pos_w1, const float* __restrict__ pos_b1,
    const float* __restrict__ pos_w2, const float* __restrict__ pos_b2,
    const float* __restrict__ bgpos_w1, const float* __restrict__ bgpos_b1,
    const float* __restrict__ bgpos_w2, const float* __restrict__ bgpos_b2,
    const float* __restrict__ rot_w1, const float* __restrict__ rot_b1,
    const float* __restrict__ rot_w2, const float* __restrict__ rot_b2,
    const float* __restrict__ shs_w1, const float* __restrict__ shs_b1,
    const float* __restrict__ shs_w2, const float* __restrict__ shs_b2,
    float* __restrict__ out, int n)
{
    extern __shared__ float sm[];
    float* sA    = sm + SA_OFF;
    float* sB    = sm + SB_OFF;
    float* sF    = sm + SF_OFF;
    float* sH1   = sm + SH1_OFF;
    float* sBias = sm + SBIAS_OFF;
    __shared__ int sidx[64];
    __shared__ int s_meta[3];

    const int t = threadIdx.x;
    if (t == 0){
        int mc = g_cnt_m;
        int mb = (mc + 63) >> 6;
        int bid = blockIdx.x;
        int seg, start, cnt;
        if (bid < mb){ seg = 0; start = bid << 6; cnt = min(64, mc - start); }
        else {
            int uc = n - mc;
            start = (bid - mb) << 6;
            seg = 1;
            cnt = (start < uc) ? min(64, uc - start) : 0;
        }
        s_meta[0] = seg; s_meta[1] = cnt; s_meta[2] = start;
    }
    __syncthreads();
    const int cnt = s_meta[1];
    if (cnt <= 0) return;
    const int seg = s_meta[0], start = s_meta[2];
    if (t < 64){
        int j = (t < cnt) ? t : 0;
        sidx[t] = (seg == 0) ? g_idx[start + j] : g_idx[n - 1 - (start + j)];
    }
    __syncthreads();

    // feat -> sF (swizzled tf32)
    phaseA(seg ? bg_sp : tgt_sp, seg ? bg_tp : tgt_tp, rays, tim, sidx, sF);
    __syncthreads();

    float acc[2][8][4];

    // stem: h = relu(feat @ st_w + st_b) -> sA (swizzled tf32)
    mma_gemm(acc, seg ? bg_st_w : st_w, seg ? bg_st_b : st_b, sF, 64, 1, sB, sBias);
    epi_to_sA(acc, sBias, sA);
    // (no sync needed: next gemm's first __syncthreads covers it)

    if (seg == 0){
        const float* w1s[3] = {pos_w1, rot_w1, shs_w1};
        const float* b1s[3] = {pos_b1, rot_b1, shs_b1};
        const float* w2s[3] = {pos_w2, rot_w2, shs_w2};
        const float* b2s[3] = {pos_b2, rot_b2, shs_b2};
        const int    wn [3] = {768, 1024, 12288};
        #pragma unroll 1
        for (int h = 0; h < 3; h++){
            mma_gemm(acc, w1s[h], b1s[h], sA, 256, 4, sB, sBias);
            __syncthreads();                  // all warps done reading sB (w1)
            epi_to_h1(acc, sBias, sH1);
            for (int i = t; i < wn[h]; i += 256) sB[i] = w2s[h][i];
            __syncthreads();
            if (h == 0){
                head3(sH1, sB, b2s[0], rays, out, sidx);
            } else if (h == 1){
                int pt = t >> 2, col = t & 3;
                float a2 = b2s[1][col];
                const float* hh = sH1 + pt*257;
                #pragma unroll 8
                for (int k = 0; k < 256; k++) a2 += hh[k]*sB[k*4 + col];
                int gi = sidx[pt];
                out[(size_t)3*n + (size_t)gi*4 + col] = rot_emb[gi*4 + col] + a2;
            } else {
                int pt = t & 63, cg = t >> 6;
                int c0 = cg*12;
                float a2[12];
                #pragma unroll
                for (int j = 0; j < 12; j++) a2[j] = b2s[2][c0 + j];
                const float* hh = sH1 + pt*257;
                #pragma unroll 4
                for (int k = 0; k < 256; k++){
                    float a = hh[k];
                    const float4* w4 = (const float4*)(sB + k*48 + c0);
                    float4 bv0 = w4[0], bv1 = w4[1], bv2 = w4[2];
                    a2[0]  += a*bv0.x; a2[1]  += a*bv0.y; a2[2]  += a*bv0.z; a2[3]  += a*bv0.w;
                    a2[4]  += a*bv1.x; a2[5]  += a*bv1.y; a2[6]  += a*bv1.z; a2[7]  += a*bv1.w;
                    a2[8]  += a*bv2.x; a2[9]  += a*bv2.y; a2[10] += a*bv2.z; a2[11] += a*bv2.w;
                }
                int gi = sidx[pt];
                const float* se = shs_emb + (size_t)gi*48 + c0;
                float* od = out + (size_t)8*n + (size_t)gi*48 + c0;
                #pragma unroll
                for (int j = 0; j < 12; j++) od[j] = se[j] + a2[j];
            }
            __syncthreads();
        }
    } else {
        mma_gemm(acc, bgpos_w1, bgpos_b1, sA, 256, 4, sB, sBias);
        __syncthreads();
        epi_to_h1(acc, sBias, sH1);
        for (int i = t; i < 768; i += 256) sB[i] = bgpos_w2[i];
        __syncthreads();
        head3(sH1, sB, bgpos_b2, rays, out, sidx);
    }
}

extern "C" void kernel_launch(void* const* d_in, const int* in_sizes, int n_in,
                              void* d_out, int out_size) {
    const float* rays    = (const float*)d_in[0];
    const float* rot_emb = (const float*)d_in[1];
    const float* shs_emb = (const float*)d_in[3];
    const float* tim     = (const float*)d_in[5];
    const float* h_emb   = (const float*)d_in[6];
    const void*  mask    = d_in[7];
    const float* tgt_sp  = (const float*)d_in[8];
    const float* tgt_tp  = (const float*)d_in[9];
    const float* bg_sp   = (const float*)d_in[10];
    const float* bg_tp   = (const float*)d_in[11];
    const float* st_w    = (const float*)d_in[12];
    const float* st_b    = (const float*)d_in[13];
    const float* bg_st_w = (const float*)d_in[14];
    const float* bg_st_b = (const float*)d_in[15];
    const float* pos_w1  = (const float*)d_in[16];
    const float* pos_b1  = (const float*)d_in[17];
    const float* pos_w2  = (const float*)d_in[18];
    const float* pos_b2  = (const float*)d_in[19];
    const float* bgpos_w1= (const float*)d_in[20];
    const float* bgpos_b1= (const float*)d_in[21];
    const float* bgpos_w2= (const float*)d_in[22];
    const float* bgpos_b2= (const float*)d_in[23];
    const float* rot_w1  = (const float*)d_in[24];
    const float* rot_b1  = (const float*)d_in[25];
    const float* rot_w2  = (const float*)d_in[26];
    const float* rot_b2  = (const float*)d_in[27];
    const float* shs_w1  = (const float*)d_in[28];
    const float* shs_b1  = (const float*)d_in[29];
    const float* shs_w2  = (const float*)d_in[30];
    const float* shs_b2  = (const float*)d_in[31];
    float* out = (float*)d_out;
    int n = in_sizes[0] / 3;

    cudaFuncSetAttribute(main_kernel, cudaFuncAttributeMaxDynamicSharedMemorySize, SMEM_BYTES);

    setup_kernel<<<1, 256>>>((const unsigned char*)mask);
    elem_kernel<<<(n + 255)/256, 256>>>(rot_emb, shs_emb, tim, h_emb, mask, out, n);
    int nb = (n + 63)/64 + 1;
    main_kernel<<<nb, 256, SMEM_BYTES>>>(
        rays, rot_emb, shs_emb, tim,
        tgt_sp, tgt_tp, bg_sp, bg_tp,
        st_w, st_b, bg_st_w, bg_st_b,
        pos_w1, pos_b1, pos_w2, pos_b2,
        bgpos_w1, bgpos_b1, bgpos_w2, bgpos_b2,
        rot_w1, rot_b1, rot_w2, rot_b2,
        shs_w1, shs_b1, shs_w2, shs_b2,
        out, n);
}

// round 4
// speedup vs baseline: 3.5274x; 3.2291x over previous
#include <cuda_runtime.h>
#include <cuda_bf16.h>
#include <math.h>

#define NMAX 400000
typedef unsigned int uint32;

__device__ int g_cnt_m;
__device__ int g_cnt_u;
__device__ int g_mask_mode;
__device__ int g_idx[NMAX];

// ---------------- weight image (bf16, pre-swizzled, chunk-major) ----------------
#define IMG_ST       0
#define IMG_BGST     8192
#define IMG_POSW1    16384
#define IMG_BGPOSW1  49152
#define IMG_ROTW1    81920
#define IMG_SHSW1    114688
#define IMG_POSW2    147456
#define IMG_ROTW2    148480
#define IMG_SHSW2    149504
#define IMG_BGPOSW2  155648
#define IMG_TOTAL    156672
__device__ uint32 g_wimg[IMG_TOTAL];

// ---------------- smem layout (u32 units) ----------------
#define SF_U   0          // feat: 128 rows x 32 words
#define SA_U   4096       // h:    128 rows x 128 words
#define SB_U   20480      // weight chunks 2 x 8192 / h1: 128 x 128 words
#define SW2_U  36864      // w2 images: up to 8192 words
#define TOTAL_U 45056
#define SMEM_BYTES (TOTAL_U*4)

// ---------------- helpers ----------------
static __device__ __forceinline__ float sigm(float x){ return 1.0f/(1.0f+expf(-x)); }
static __device__ __forceinline__ uint32 bpack(float a, float b){
    __nv_bfloat162 h = __float22bfloat162_rn(make_float2(a,b));
    return *reinterpret_cast<uint32*>(&h);
}
static __device__ __forceinline__ void ldsm4(uint32* r, uint32 addr){
    asm volatile("ldmatrix.sync.aligned.m8n8.x4.shared.b16 {%0,%1,%2,%3},[%4];"
      : "=r"(r[0]),"=r"(r[1]),"=r"(r[2]),"=r"(r[3]) : "r"(addr));
}
static __device__ __forceinline__ void ldsm2(uint32* r, uint32 addr){
    asm volatile("ldmatrix.sync.aligned.m8n8.x2.shared.b16 {%0,%1},[%2];"
      : "=r"(r[0]),"=r"(r[1]) : "r"(addr));
}
static __device__ __forceinline__ void mma16(float* d, const uint32* a, uint32 b0, uint32 b1){
    asm volatile("mma.sync.aligned.m16n8k16.row.col.f32.bf16.bf16.f32 "
      "{%0,%1,%2,%3},{%4,%5,%6,%7},{%8,%9},{%0,%1,%2,%3};"
      : "+f"(d[0]),"+f"(d[1]),"+f"(d[2]),"+f"(d[3])
      : "r"(a[0]),"r"(a[1]),"r"(a[2]),"r"(a[3]),"r"(b0),"r"(b1));
}
static __device__ __forceinline__ void cpa16(uint32 saddr, const void* g){
    asm volatile("cp.async.cg.shared.global [%0],[%1],16;" :: "r"(saddr), "l"(g));
}
static __device__ __forceinline__ void cp_commit(){ asm volatile("cp.async.commit_group;"); }
template<int N> static __device__ __forceinline__ void cp_wait(){ asm volatile("cp.async.wait_group %0;"::"n"(N)); }

// ---------------- convert kernel: f32 weights -> swizzled bf16 images ----------------
__global__ void convert_kernel(const float* st_w, const float* bg_st_w,
    const float* pos_w1, const float* bgpos_w1, const float* rot_w1, const float* shs_w1,
    const float* pos_w2, const float* rot_w2, const float* shs_w2, const float* bgpos_w2)
{
    int i = blockIdx.x*blockDim.x + threadIdx.x;
    if (i >= IMG_TOTAL) return;
    const float* src; int N, Npad, base;
    if      (i < IMG_BGST)   { src=st_w;    N=256; Npad=256; base=IMG_ST; }
    else if (i < IMG_POSW1)  { src=bg_st_w; N=256; Npad=256; base=IMG_BGST; }
    else if (i < IMG_BGPOSW1){ src=pos_w1;  N=256; Npad=256; base=IMG_POSW1; }
    else if (i < IMG_ROTW1)  { src=bgpos_w1;N=256; Npad=256; base=IMG_BGPOSW1; }
    else if (i < IMG_SHSW1)  { src=rot_w1;  N=256; Npad=256; base=IMG_ROTW1; }
    else if (i < IMG_POSW2)  { src=shs_w1;  N=256; Npad=256; base=IMG_SHSW1; }
    else if (i < IMG_ROTW2)  { src=pos_w2;  N=3;   Npad=8;   base=IMG_POSW2; }
    else if (i < IMG_SHSW2)  { src=rot_w2;  N=4;   Npad=8;   base=IMG_ROTW2; }
    else if (i < IMG_BGPOSW2){ src=shs_w2;  N=48;  Npad=48;  base=IMG_SHSW2; }
    else                     { src=bgpos_w2;N=3;   Npad=8;   base=IMG_BGPOSW2; }
    int wi = i - base;
    int wpc = Npad*32;
    int chunk = wi / wpc, r = wi % wpc;
    int nrow = r >> 5, pw = r & 31;
    int q = (pw>>2) ^ (nrow&7);
    int p = (q<<2) | (pw&3);
    int k = chunk*64 + 2*p;
    float lo = 0.0f, hi = 0.0f;
    if (nrow < N){ lo = src[(size_t)k*N + nrow]; hi = src[(size_t)(k+1)*N + nrow]; }
    g_wimg[i] = bpack(lo, hi);
}

// ---------------- setup: mask dtype sniff + counter reset ----------------
__global__ void setup_kernel(const unsigned char* __restrict__ mb){
    __shared__ int s3f, s3f1, s1off;
    if (threadIdx.x == 0){ s3f = 0; s3f1 = 0; s1off = 0; }
    __syncthreads();
    int a = 0, b = 0, c = 0;
    for (int i = threadIdx.x; i < 4096; i += blockDim.x){
        unsigned v = mb[i];
        if (v == 0x3fu){ a = 1; if ((i & 3) == 1) b = 1; }
        if (v == 0x01u && (i & 3) != 0) c = 1;
    }
    if (a) atomicOr(&s3f, 1);
    if (b) atomicOr(&s3f1, 1);
    if (c) atomicOr(&s1off, 1);
    __syncthreads();
    if (threadIdx.x == 0){
        int mode;
        if (s3f) mode = s3f1 ? 3 : 2;
        else     mode = s1off ? 0 : 1;
        g_mask_mode = mode;
        g_cnt_m = 0;
        g_cnt_u = 0;
    }
}

static __device__ __forceinline__ bool read_mask(const void* m, int i, int mode){
    if (mode == 0) return ((const unsigned char*)m)[i] != 0;
    if (mode == 1) return ((const int*)m)[i] != 0;
    if (mode == 2) return ((const float*)m)[i] != 0.0f;
    return ((const unsigned short*)m)[i] != 0;
}

// ---------------- elementwise: opacity, passthroughs, mask partition ----------------
__global__ void elem_kernel(const float* __restrict__ rot_emb, const float* __restrict__ shs_emb,
                            const float* __restrict__ tim, const float* __restrict__ h_emb,
                            const void* __restrict__ mask, float* __restrict__ out, int n){
    __shared__ int sm_m, sm_u, base_m, base_u;
    if (threadIdx.x == 0){ sm_m = 0; sm_u = 0; }
    __syncthreads();
    int i = blockIdx.x*blockDim.x + threadIdx.x;
    bool valid = (i < n);
    int mode = g_mask_mode;
    bool msk = false;
    int pos = 0;
    if (valid){
        msk = read_mask(mask, i, mode);
        pos = msk ? atomicAdd(&sm_m, 1) : atomicAdd(&sm_u, 1);
    }
    __syncthreads();
    if (threadIdx.x == 0){
        base_m = atomicAdd(&g_cnt_m, sm_m);
        base_u = atomicAdd(&g_cnt_u, sm_u);
    }
    __syncthreads();
    if (!valid) return;
    float t0 = tim[0];
    float he0 = h_emb[3*i], he1 = h_emb[3*i+1], he2 = h_emb[3*i+2];
    float op;
    if (msk){
        float mu = sigm(he2);
        float w  = he1*he1;
        float d  = t0 - mu;
        op = expf(-w*d*d);
    } else {
        op = sigm(he0);
    }
    out[(size_t)7*n + i] = op;
    if (msk){
        g_idx[base_m + pos] = i;
    } else {
        g_idx[n - 1 - (base_u + pos)] = i;
        ((float4*)(out + (size_t)3*n))[i] = ((const float4*)rot_emb)[i];
        const float4* s4 = (const float4*)shs_emb + (size_t)i*12;
        float4* d4 = (float4*)(out + (size_t)8*n) + (size_t)i*12;
        #pragma unroll
        for (int q = 0; q < 12; q++) d4[q] = s4[q];
    }
}

// ---------------- big GEMM: 128x256, A (bf16, swizzled) in smem, B staged from g_wimg ----------------
static __device__ __forceinline__ void gemm_big(
    float acc[2][16][4], const uint32* gimg, uint32 smem_base,
    uint32 aBaseByte, int rowBytes, int kchunks, bool stage0_done)
{
    const int t = threadIdx.x;
    const int lane = t & 31, w = t >> 5;
    const int wm = w >> 1, wn = w & 1;
    const int mb = wm*32, nb = wn*128;
    const int l7 = lane & 7, lm = lane >> 3;
    const int a_rl = l7 + ((lm & 1) << 3);
    const int a_qo = lm >> 1;
    const int b_kh = lm & 1;
    const int b_no = (lm >> 1) << 3;
    const int b_r7 = (b_no + l7) & 7;

    #pragma unroll
    for (int mt = 0; mt < 2; mt++)
        #pragma unroll
        for (int nt = 0; nt < 16; nt++)
            #pragma unroll
            for (int i = 0; i < 4; i++) acc[mt][nt][i] = 0.0f;

    const uint32 Ab0 = aBaseByte + (uint32)(mb + a_rl) * rowBytes;
    const uint32 Ab1 = Ab0 + 16u * rowBytes;
    const uint32 Bthread = (uint32)(nb + b_no + l7) * 128u;
    const bool bigA = (rowBytes == 512);

    if (!stage0_done){
        uint32 dst = smem_base + (SB_U + t*32)*4;
        const uint32* s = gimg + t*32;
        #pragma unroll
        for (int j = 0; j < 8; j++) cpa16(dst + j*16, s + j*4);
        cp_commit();
    }
    for (int c = 0; c < kchunks; c++){
        if (c + 1 < kchunks){
            uint32 dst = smem_base + (SB_U + ((c+1)&1)*8192 + t*32)*4;
            const uint32* s = gimg + (c+1)*8192 + t*32;
            #pragma unroll
            for (int j = 0; j < 8; j++) cpa16(dst + j*16, s + j*4);
            cp_commit();
            cp_wait<1>();
        } else {
            cp_wait<0>();
        }
        __syncthreads();
        uint32 sBcur = smem_base + (SB_U + (c&1)*8192)*4;
        #pragma unroll
        for (int ks = 0; ks < 4; ks++){
            uint32 ar[2][4];
            int qA = (bigA ? c*8 : 0) + ks*2 + a_qo;
            uint32 axor = (uint32)((qA ^ l7) << 4);
            ldsm4(ar[0], Ab0 + axor);
            ldsm4(ar[1], Ab1 + axor);
            uint32 bxor = (uint32)((((ks*2 + b_kh) ^ b_r7)) << 4);
            #pragma unroll
            for (int half = 0; half < 2; half++){
                uint32 br[4][4];
                #pragma unroll
                for (int j = 0; j < 4; j++){
                    int ntp = half*4 + j;
                    ldsm4(br[j], sBcur + Bthread + (uint32)(ntp*16*128) + bxor);
                }
                #pragma unroll
                for (int j = 0; j < 4; j++){
                    #pragma unroll
                    for (int mt = 0; mt < 2; mt++){
                        mma16(acc[mt][half*8 + 2*j],     ar[mt], br[j][0], br[j][1]);
                        mma16(acc[mt][half*8 + 2*j + 1], ar[mt], br[j][2], br[j][3]);
                    }
                }
            }
        }
        __syncthreads();
    }
}

// epilogue: acc -> bf16 A-layout (bias + relu), dst row stride 128 words
static __device__ __forceinline__ void epi_big(
    float acc[2][16][4], const float* __restrict__ gb, uint32* __restrict__ dstU)
{
    const int t = threadIdx.x;
    const int lane = t & 31, w = t >> 5;
    const int wm = w >> 1, wn = w & 1;
    const int mb = wm*32, nb = wn*128;
    const int g = lane >> 2, tig = lane & 3;
    #pragma unroll
    for (int mt = 0; mt < 2; mt++){
        int r0 = mb + mt*16 + g, r1 = r0 + 8;
        #pragma unroll
        for (int nt = 0; nt < 16; nt++){
            int col = nb + nt*8 + 2*tig;
            float b0 = gb[col], b1 = gb[col+1];
            uint32 w0 = bpack(fmaxf(acc[mt][nt][0] + b0, 0.0f), fmaxf(acc[mt][nt][1] + b1, 0.0f));
            uint32 w1 = bpack(fmaxf(acc[mt][nt][2] + b0, 0.0f), fmaxf(acc[mt][nt][3] + b1, 0.0f));
            int p = wn*64 + nt*4 + tig;
            int phys = (((p>>2) ^ (g & 7)) << 2) | (p & 3);
            dstU[r0*128 + phys] = w0;
            dstU[r1*128 + phys] = w1;
        }
    }
}

// ---------------- small w2 GEMMs (A = h1 in sB region) ----------------
static __device__ __forceinline__ void gemm_w2_n8(
    float acc8[4], uint32 smem_base, int w2off_u)
{
    const int t = threadIdx.x;
    const int lane = t & 31, w = t >> 5;
    const int mb = w*16;
    const int l7 = lane & 7, lm = lane >> 3;
    const int a_rl = l7 + ((lm & 1) << 3);
    const int a_qo = lm >> 1;
    const int b_kh2 = lm & 1;
    #pragma unroll
    for (int i = 0; i < 4; i++) acc8[i] = 0.0f;
    const uint32 Ab = smem_base + SB_U*4 + (uint32)(mb + a_rl)*512u;
    const uint32 Bb = smem_base + (SW2_U + w2off_u)*4 + (uint32)l7*128u;
    #pragma unroll
    for (int c = 0; c < 4; c++){
        #pragma unroll
        for (int ks = 0; ks < 4; ks++){
            uint32 ar[4];
            int qA = c*8 + ks*2 + a_qo;
            ldsm4(ar, Ab + (uint32)((qA ^ l7) << 4));
            uint32 br[2];
            ldsm2(br, Bb + (uint32)(c*1024) + (uint32)(((ks*2 + b_kh2) ^ l7) << 4));
            mma16(acc8, ar, br[0], br[1]);
        }
    }
}

static __device__ __forceinline__ void gemm_w2_n48(
    float acc48[6][4], uint32 smem_base, int w2off_u)
{
    const int t = threadIdx.x;
    const int lane = t & 31, w = t >> 5;
    const int mb = w*16;
    const int l7 = lane & 7, lm = lane >> 3;
    const int a_rl = l7 + ((lm & 1) << 3);
    const int a_qo = lm >> 1;
    const int b_kh = lm & 1;
    const int b_no = (lm >> 1) << 3;
    const int b_r7 = (b_no + l7) & 7;
    #pragma unroll
    for (int nt = 0; nt < 6; nt++)
        #pragma unroll
        for (int i = 0; i < 4; i++) acc48[nt][i] = 0.0f;
    const uint32 Ab = smem_base + SB_U*4 + (uint32)(mb + a_rl)*512u;
    const uint32 Bb = smem_base + (SW2_U + w2off_u)*4 + (uint32)(b_no + l7)*128u;
    #pragma unroll
    for (int c = 0; c < 4; c++){
        #pragma unroll
        for (int ks = 0; ks < 4; ks++){
            uint32 ar[4];
            int qA = c*8 + ks*2 + a_qo;
            ldsm4(ar, Ab + (uint32)((qA ^ l7) << 4));
            uint32 bxor = (uint32)(((ks*2 + b_kh) ^ b_r7) << 4);
            #pragma unroll
            for (int ntp = 0; ntp < 3; ntp++){
                uint32 br[4];
                ldsm4(br, Bb + (uint32)(c*48*128) + (uint32)(ntp*16*128) + bxor);
                mma16(acc48[2*ntp],   ar, br[0], br[1]);
                mma16(acc48[2*ntp+1], ar, br[2], br[3]);
            }
        }
    }
}

// ---------------- phase A: K-planes bilinear sampling -> sF (bf16 A-layout) ----------------
static __device__ __forceinline__ void phaseA(
    const float* __restrict__ sp, const float* __restrict__ tp,
    const float* __restrict__ rays, const float* __restrict__ tim,
    const int* sidx, uint32* __restrict__ sF)
{
    const int t = threadIdx.x;
    const int pt = t >> 1, fg = t & 1;
    const int gi = sidx[pt];
    float px = rays[3*gi], py = rays[3*gi+1], pz = rays[3*gi+2];
    float tv = tim[gi];
    float cx = fminf(fmaxf((px*(1.0f/1.3f) + 1.0f)*0.5f, 0.0f), 1.0f) * 127.0f;
    float cy = fminf(fmaxf((py*(1.0f/1.3f) + 1.0f)*0.5f, 0.0f), 1.0f) * 127.0f;
    float cz = fminf(fmaxf((pz*(1.0f/1.3f) + 1.0f)*0.5f, 0.0f), 1.0f) * 127.0f;
    float tq = fminf(fmaxf(tv, 0.0f), 1.0f) * 63.0f;

    const float* PB[6];
    int O00[6], O10[6], O01[6], O11[6];
    float W00[6], W10[6], W01[6], W11[6];

#define SETP(s, bp, R2, uu, vv) { \
    float u_ = fminf(fmaxf((uu), 0.0f), 127.0f); \
    float v_ = fminf(fmaxf((vv), 0.0f), (float)((R2)-1)); \
    int i0 = (int)u_; int j0 = (int)v_; \
    int i1 = min(i0+1, 127); int j1 = min(j0+1, (R2)-1); \
    float fu = u_ - (float)i0, fv = v_ - (float)j0; \
    PB[s] = (bp); \
    O00[s] = (i0*(R2)+j0)*64; O10[s] = (i1*(R2)+j0)*64; \
    O01[s] = (i0*(R2)+j1)*64; O11[s] = (i1*(R2)+j1)*64; \
    W00[s] = (1.0f-fu)*(1.0f-fv); W10[s] = fu*(1.0f-fv); \
    W01[s] = (1.0f-fu)*fv;        W11[s] = fu*fv; }

    SETP(0, sp,           128, cx, cy)
    SETP(1, sp + 1048576, 128, cx, cz)
    SETP(2, sp + 2097152, 128, cy, cz)
    SETP(3, tp,            64, cx, tq)
    SETP(4, tp + 524288,   64, cy, tq)
    SETP(5, tp + 1048576,  64, cz, tq)
#undef SETP

    #pragma unroll
    for (int q = 0; q < 8; q++){
        int f = fg*32 + q*4;
        float r0 = 1.0f, r1 = 1.0f, r2 = 1.0f, r3 = 1.0f;
        #pragma unroll
        for (int s = 0; s < 6; s++){
            const float* b = PB[s] + f;
            float4 v00 = *(const float4*)(b + O00[s]);
            float4 v10 = *(const float4*)(b + O10[s]);
            float4 v01 = *(const float4*)(b + O01[s]);
            float4 v11 = *(const float4*)(b + O11[s]);
            float sx = v00.x*W00[s] + v10.x*W10[s] + v01.x*W01[s] + v11.x*W11[s];
            float sy = v00.y*W00[s] + v10.y*W10[s] + v01.y*W01[s] + v11.y*W11[s];
            float sz = v00.z*W00[s] + v10.z*W10[s] + v01.z*W01[s] + v11.z*W11[s];
            float sw_ = v00.w*W00[s] + v10.w*W10[s] + v01.w*W01[s] + v11.w*W11[s];
            r0 *= sx; r1 *= sy; r2 *= sz; r3 *= sw_;
        }
        int p0 = fg*16 + q*2;
        int phys0 = (((p0>>2) ^ (pt & 7)) << 2) | (p0 & 3);
        int p1 = p0 + 1;
        int phys1 = (((p1>>2) ^ (pt & 7)) << 2) | (p1 & 3);
        sF[pt*32 + phys0] = bpack(r0, r1);
        sF[pt*32 + phys1] = bpack(r2, r3);
    }
}

// ---------------- main kernel ----------------
__global__ void __launch_bounds__(256, 1) main_kernel(
    const float* __restrict__ rays, const float* __restrict__ rot_emb,
    const float* __restrict__ shs_emb, const float* __restrict__ tim,
    const float* __restrict__ tgt_sp, const float* __restrict__ tgt_tp,
    const float* __restrict__ bg_sp,  const float* __restrict__ bg_tp,
    const float* __restrict__ st_b,   const float* __restrict__ bg_st_b,
    const float* __restrict__ pos_b1, const float* __restrict__ pos_b2,
    const float* __restrict__ bgpos_b1, const float* __restrict__ bgpos_b2,
    const float* __restrict__ rot_b1, const float* __restrict__ rot_b2,
    const float* __restrict__ shs_b1, const float* __restrict__ shs_b2,
    float* __restrict__ out, int n)
{
    extern __shared__ uint32 smu[];
    const uint32 smem_base = (uint32)__cvta_generic_to_shared(smu);
    __shared__ int sidx[128];
    __shared__ int s_meta[3];

    const int t = threadIdx.x;
    if (t == 0){
        int mc = g_cnt_m;
        int mtiles = (mc + 127) >> 7;
        int bid = blockIdx.x;
        int seg, start, cnt;
        if (bid < mtiles){ seg = 0; start = bid << 7; cnt = min(128, mc - start); }
        else {
            int uc = n - mc;
            start = (bid - mtiles) << 7;
            seg = 1;
            cnt = (start < uc) ? min(128, uc - start) : 0;
        }
        s_meta[0] = seg; s_meta[1] = cnt; s_meta[2] = start;
    }
    __syncthreads();
    const int cnt = s_meta[1];
    if (cnt <= 0) return;
    const int seg = s_meta[0], start = s_meta[2];
    if (t < 128){
        int j = (t < cnt) ? t : 0;
        sidx[t] = (seg == 0) ? g_idx[start + j] : g_idx[n - 1 - (start + j)];
    }
    __syncthreads();

    // prologue staging: stem chunk -> sB buf0, w2 images -> sW2
    {
        const uint32* stem_img = g_wimg + (seg ? IMG_BGST : IMG_ST);
        uint32 dst = smem_base + (SB_U + t*32)*4;
        const uint32* s = stem_img + t*32;
        #pragma unroll
        for (int j = 0; j < 8; j++) cpa16(dst + j*16, s + j*4);
        if (seg == 0){
            uint32 d2 = smem_base + (SW2_U + t*32)*4;
            const uint32* s2 = g_wimg + IMG_POSW2 + t*32;
            #pragma unroll
            for (int j = 0; j < 8; j++) cpa16(d2 + j*16, s2 + j*4);
        } else {
            cpa16(smem_base + (SW2_U + t*4)*4, g_wimg + IMG_BGPOSW2 + t*4);
        }
        cp_commit();
    }

    phaseA(seg ? bg_sp : tgt_sp, seg ? bg_tp : tgt_tp, rays, tim, sidx, smu + SF_U);
    cp_wait<0>();
    __syncthreads();

    float acc[2][16][4];

    // stem: h = relu(feat @ st_w + b) -> sA
    gemm_big(acc, g_wimg, smem_base, smem_base + SF_U*4, 128, 1, true);
    epi_big(acc, seg ? bg_st_b : st_b, smu + SA_U);
    __syncthreads();

    const int lane = t & 31, w = t >> 5;
    const int g = lane >> 2, tig = lane & 3;
    const int mb2 = w*16;

    if (seg == 0){
        // ---- pos head ----
        gemm_big(acc, g_wimg + IMG_POSW1, smem_base, smem_base + SA_U*4, 512, 4, false);
        epi_big(acc, pos_b1, smu + SB_U);
        __syncthreads();
        {
            float a8[4];
            gemm_w2_n8(a8, smem_base, 0);
            #pragma unroll
            for (int i = 0; i < 2; i++){
                int pt = mb2 + g + 8*i;
                int gi = sidx[pt];
                #pragma unroll
                for (int jj = 0; jj < 2; jj++){
                    int col = 2*tig + jj;
                    if (col < 3){
                        float d = a8[i*2+jj] + pos_b2[col];
                        out[(size_t)gi*3 + col] = rays[gi*3 + col] + d;
                    }
                }
            }
        }
        __syncthreads();
        // ---- rot head ----
        gemm_big(acc, g_wimg + IMG_ROTW1, smem_base, smem_base + SA_U*4, 512, 4, false);
        epi_big(acc, rot_b1, smu + SB_U);
        __syncthreads();
        {
            float a8[4];
            gemm_w2_n8(a8, smem_base, 1024);
            #pragma unroll
            for (int i = 0; i < 2; i++){
                int pt = mb2 + g + 8*i;
                int gi = sidx[pt];
                #pragma unroll
                for (int jj = 0; jj < 2; jj++){
                    int col = 2*tig + jj;
                    if (col < 4){
                        float d = a8[i*2+jj] + rot_b2[col];
                        out[(size_t)3*n + (size_t)gi*4 + col] = rot_emb[(size_t)gi*4 + col] + d;
                    }
                }
            }
        }
        __syncthreads();
        // ---- shs head ----
        gemm_big(acc, g_wimg + IMG_SHSW1, smem_base, smem_base + SA_U*4, 512, 4, false);
        epi_big(acc, shs_b1, smu + SB_U);
        __syncthreads();
        {
            float a48[6][4];
            gemm_w2_n48(a48, smem_base, 2048);
            float* o8 = out + (size_t)8*n;
            #pragma unroll
            for (int i = 0; i < 2; i++){
                int pt = mb2 + g + 8*i;
                int gi = sidx[pt];
                const float* se = shs_emb + (size_t)gi*48;
                float* od = o8 + (size_t)gi*48;
                #pragma unroll
                for (int nt = 0; nt < 6; nt++){
                    #pragma unroll
                    for (int jj = 0; jj < 2; jj++){
                        int col = nt*8 + 2*tig + jj;
                        float d = a48[nt][i*2+jj] + shs_b2[col];
                        od[col] = se[col] + d;
                    }
                }
            }
        }
    } else {
        // ---- bgpos head ----
        gemm_big(acc, g_wimg + IMG_BGPOSW1, smem_base, smem_base + SA_U*4, 512, 4, false);
        epi_big(acc, bgpos_b1, smu + SB_U);
        __syncthreads();
        {
            float a8[4];
            gemm_w2_n8(a8, smem_base, 0);
            #pragma unroll
            for (int i = 0; i < 2; i++){
                int pt = mb2 + g + 8*i;
                int gi = sidx[pt];
                #pragma unroll
                for (int jj = 0; jj < 2; jj++){
                    int col = 2*tig + jj;
                    if (col < 3){
                        float d = a8[i*2+jj] + bgpos_b2[col];
                        out[(size_t)gi*3 + col] = rays[gi*3 + col] + d;
                    }
                }
            }
        }
    }
}

extern "C" void kernel_launch(void* const* d_in, const int* in_sizes, int n_in,
                              void* d_out, int out_size) {
    const float* rays    = (const float*)d_in[0];
    const float* rot_emb = (const float*)d_in[1];
    const float* shs_emb = (const float*)d_in[3];
    const float* tim     = (const float*)d_in[5];
    const float* h_emb   = (const float*)d_in[6];
    const void*  mask    = d_in[7];
    const float* tgt_sp  = (const float*)d_in[8];
    const float* tgt_tp  = (const float*)d_in[9];
    const float* bg_sp   = (const float*)d_in[10];
    const float* bg_tp   = (const float*)d_in[11];
    const float* st_w    = (const float*)d_in[12];
    const float* st_b    = (const float*)d_in[13];
    const float* bg_st_w = (const float*)d_in[14];
    const float* bg_st_b = (const float*)d_in[15];
    const float* pos_w1  = (const float*)d_in[16];
    const float* pos_b1  = (const float*)d_in[17];
    const float* pos_w2  = (const float*)d_in[18];
    const float* pos_b2  = (const float*)d_in[19];
    const float* bgpos_w1= (const float*)d_in[20];
    const float* bgpos_b1= (const float*)d_in[21];
    const float* bgpos_w2= (const float*)d_in[22];
    const float* bgpos_b2= (const float*)d_in[23];
    const float* rot_w1  = (const float*)d_in[24];
    const float* rot_b1  = (const float*)d_in[25];
    const float* rot_w2  = (const float*)d_in[26];
    const float* rot_b2  = (const float*)d_in[27];
    const float* shs_w1  = (const float*)d_in[28];
    const float* shs_b1  = (const float*)d_in[29];
    const float* shs_w2  = (const float*)d_in[30];
    const float* shs_b2  = (const float*)d_in[31];
    float* out = (float*)d_out;
    int n = in_sizes[0] / 3;

    cudaFuncSetAttribute(main_kernel, cudaFuncAttributeMaxDynamicSharedMemorySize, SMEM_BYTES);

    convert_kernel<<<(IMG_TOTAL + 255)/256, 256>>>(
        st_w, bg_st_w, pos_w1, bgpos_w1, rot_w1, shs_w1,
        pos_w2, rot_w2, shs_w2, bgpos_w2);
    setup_kernel<<<1, 256>>>((const unsigned char*)mask);
    elem_kernel<<<(n + 255)/256, 256>>>(rot_emb, shs_emb, tim, h_emb, mask, out, n);
    int nb = (n + 127)/128 + 1;
    main_kernel<<<nb, 256, SMEM_BYTES>>>(
        rays, rot_emb, shs_emb, tim,
        tgt_sp, tgt_tp, bg_sp, bg_tp,
        st_b, bg_st_b,
        pos_b1, pos_b2, bgpos_b1, bgpos_b2,
        rot_b1, rot_b2, shs_b1, shs_b2,
        out, n);
}

// round 5
// speedup vs baseline: 5.0994x; 1.4456x over previous
#include <cuda_runtime.h>
#include <cuda_bf16.h>
#include <math.h>

#define NMAX 400000
typedef unsigned int uint32;

__device__ int g_cnt_m;
__device__ int g_cnt_u;
__device__ int g_mask_mode;
__device__ int g_idx[NMAX];

// ---------------- weight image (bf16, pre-swizzled, chunk-major) ----------------
#define IMG_ST       0
#define IMG_BGST     8192
#define IMG_POSW1    16384
#define IMG_BGPOSW1  49152
#define IMG_ROTW1    81920
#define IMG_SHSW1    114688
#define IMG_POSW2    147456
#define IMG_ROTW2    148480
#define IMG_SHSW2    149504
#define IMG_BGPOSW2  155648
#define IMG_TOTAL    156672
__device__ uint32 g_wimg[IMG_TOTAL];

// ---------------- smem layout (u32 units) ----------------
#define SF_U   0          // feat: 128 rows x 32 words
#define SA_U   4096       // h:    128 rows x 128 words
#define SB_U   20480      // weight chunks 2 x 8192 / h1: 128 x 128 words
#define SW2_U  36864      // w2 images: up to 8192 words
#define TOTAL_U 45056
#define SMEM_BYTES (TOTAL_U*4)

// ---------------- helpers ----------------
static __device__ __forceinline__ float sigm(float x){ return 1.0f/(1.0f+expf(-x)); }
static __device__ __forceinline__ uint32 bpack(float a, float b){
    __nv_bfloat162 h = __float22bfloat162_rn(make_float2(a,b));
    return *reinterpret_cast<uint32*>(&h);
}
static __device__ __forceinline__ void ldsm4(uint32* r, uint32 addr){
    asm volatile("ldmatrix.sync.aligned.m8n8.x4.shared.b16 {%0,%1,%2,%3},[%4];"
      : "=r"(r[0]),"=r"(r[1]),"=r"(r[2]),"=r"(r[3]) : "r"(addr));
}
static __device__ __forceinline__ void ldsm2(uint32* r, uint32 addr){
    asm volatile("ldmatrix.sync.aligned.m8n8.x2.shared.b16 {%0,%1},[%2];"
      : "=r"(r[0]),"=r"(r[1]) : "r"(addr));
}
static __device__ __forceinline__ void mma16(float* d, const uint32* a, uint32 b0, uint32 b1){
    asm volatile("mma.sync.aligned.m16n8k16.row.col.f32.bf16.bf16.f32 "
      "{%0,%1,%2,%3},{%4,%5,%6,%7},{%8,%9},{%0,%1,%2,%3};"
      : "+f"(d[0]),"+f"(d[1]),"+f"(d[2]),"+f"(d[3])
      : "r"(a[0]),"r"(a[1]),"r"(a[2]),"r"(a[3]),"r"(b0),"r"(b1));
}
static __device__ __forceinline__ void cpa16(uint32 saddr, const void* g){
    asm volatile("cp.async.cg.shared.global [%0],[%1],16;" :: "r"(saddr), "l"(g));
}
static __device__ __forceinline__ void cp_commit(){ asm volatile("cp.async.commit_group;"); }
template<int N> static __device__ __forceinline__ void cp_wait(){ asm volatile("cp.async.wait_group %0;"::"n"(N)); }

// ---------------- convert kernel: f32 weights -> swizzled bf16 images ----------------
__global__ void convert_kernel(const float* st_w, const float* bg_st_w,
    const float* pos_w1, const float* bgpos_w1, const float* rot_w1, const float* shs_w1,
    const float* pos_w2, const float* rot_w2, const float* shs_w2, const float* bgpos_w2)
{
    int i = blockIdx.x*blockDim.x + threadIdx.x;
    if (i >= IMG_TOTAL) return;
    const float* src; int N, Npad, base;
    if      (i < IMG_BGST)   { src=st_w;    N=256; Npad=256; base=IMG_ST; }
    else if (i < IMG_POSW1)  { src=bg_st_w; N=256; Npad=256; base=IMG_BGST; }
    else if (i < IMG_BGPOSW1){ src=pos_w1;  N=256; Npad=256; base=IMG_POSW1; }
    else if (i < IMG_ROTW1)  { src=bgpos_w1;N=256; Npad=256; base=IMG_BGPOSW1; }
    else if (i < IMG_SHSW1)  { src=rot_w1;  N=256; Npad=256; base=IMG_ROTW1; }
    else if (i < IMG_POSW2)  { src=shs_w1;  N=256; Npad=256; base=IMG_SHSW1; }
    else if (i < IMG_ROTW2)  { src=pos_w2;  N=3;   Npad=8;   base=IMG_POSW2; }
    else if (i < IMG_SHSW2)  { src=rot_w2;  N=4;   Npad=8;   base=IMG_ROTW2; }
    else if (i < IMG_BGPOSW2){ src=shs_w2;  N=48;  Npad=48;  base=IMG_SHSW2; }
    else                     { src=bgpos_w2;N=3;   Npad=8;   base=IMG_BGPOSW2; }
    int wi = i - base;
    int wpc = Npad*32;
    int chunk = wi / wpc, r = wi % wpc;
    int nrow = r >> 5, pw = r & 31;
    int q = (pw>>2) ^ (nrow&7);
    int p = (q<<2) | (pw&3);
    int k = chunk*64 + 2*p;
    float lo = 0.0f, hi = 0.0f;
    if (nrow < N){ lo = src[(size_t)k*N + nrow]; hi = src[(size_t)(k+1)*N + nrow]; }
    g_wimg[i] = bpack(lo, hi);
}

// ---------------- setup: mask dtype sniff + counter reset ----------------
__global__ void setup_kernel(const unsigned char* __restrict__ mb){
    __shared__ int s3f, s3f1, s1off;
    if (threadIdx.x == 0){ s3f = 0; s3f1 = 0; s1off = 0; }
    __syncthreads();
    int a = 0, b = 0, c = 0;
    for (int i = threadIdx.x; i < 4096; i += blockDim.x){
        unsigned v = mb[i];
        if (v == 0x3fu){ a = 1; if ((i & 3) == 1) b = 1; }
        if (v == 0x01u && (i & 3) != 0) c = 1;
    }
    if (a) atomicOr(&s3f, 1);
    if (b) atomicOr(&s3f1, 1);
    if (c) atomicOr(&s1off, 1);
    __syncthreads();
    if (threadIdx.x == 0){
        int mode;
        if (s3f) mode = s3f1 ? 3 : 2;
        else     mode = s1off ? 0 : 1;
        g_mask_mode = mode;
        g_cnt_m = 0;
        g_cnt_u = 0;
    }
}

static __device__ __forceinline__ bool read_mask(const void* m, int i, int mode){
    if (mode == 0) return ((const unsigned char*)m)[i] != 0;
    if (mode == 1) return ((const int*)m)[i] != 0;
    if (mode == 2) return ((const float*)m)[i] != 0.0f;
    return ((const unsigned short*)m)[i] != 0;
}

// ---------------- elementwise: opacity, passthroughs, mask partition ----------------
__global__ void elem_kernel(const float* __restrict__ rot_emb, const float* __restrict__ shs_emb,
                            const float* __restrict__ tim, const float* __restrict__ h_emb,
                            const void* __restrict__ mask, float* __restrict__ out, int n){
    __shared__ int sm_m, sm_u, base_m, base_u;
    if (threadIdx.x == 0){ sm_m = 0; sm_u = 0; }
    __syncthreads();
    int i = blockIdx.x*blockDim.x + threadIdx.x;
    bool valid = (i < n);
    int mode = g_mask_mode;
    bool msk = false;
    int pos = 0;
    if (valid){
        msk = read_mask(mask, i, mode);
        pos = msk ? atomicAdd(&sm_m, 1) : atomicAdd(&sm_u, 1);
    }
    __syncthreads();
    if (threadIdx.x == 0){
        base_m = atomicAdd(&g_cnt_m, sm_m);
        base_u = atomicAdd(&g_cnt_u, sm_u);
    }
    __syncthreads();
    if (!valid) return;
    float t0 = tim[0];
    float he0 = h_emb[3*i], he1 = h_emb[3*i+1], he2 = h_emb[3*i+2];
    float op;
    if (msk){
        float mu = sigm(he2);
        float w  = he1*he1;
        float d  = t0 - mu;
        op = expf(-w*d*d);
    } else {
        op = sigm(he0);
    }
    out[(size_t)7*n + i] = op;
    if (msk){
        g_idx[base_m + pos] = i;
    } else {
        g_idx[n - 1 - (base_u + pos)] = i;
        ((float4*)(out + (size_t)3*n))[i] = ((const float4*)rot_emb)[i];
        const float4* s4 = (const float4*)shs_emb + (size_t)i*12;
        float4* d4 = (float4*)(out + (size_t)8*n) + (size_t)i*12;
        #pragma unroll
        for (int q = 0; q < 12; q++) d4[q] = s4[q];
    }
}

// ---------------- big GEMM: 128x256, 16 warps (4m x 4n), A bf16 swizzled in smem ----------------
static __device__ __forceinline__ void gemm_big(
    float acc[2][8][4], const uint32* gimg, uint32 smem_base,
    uint32 aBaseByte, int rowBytes, int kchunks, bool stage0_done)
{
    const int t = threadIdx.x;
    const int lane = t & 31, w = t >> 5;
    const int wm = w >> 2, wn = w & 3;
    const int mb = wm*32, nb = wn*64;
    const int l7 = lane & 7, lm = lane >> 3;
    const int a_rl = l7 + ((lm & 1) << 3);
    const int a_qo = lm >> 1;
    const int b_kh = lm & 1;
    const int b_no = (lm >> 1) << 3;
    const int b_r7 = (b_no + l7) & 7;

    #pragma unroll
    for (int mt = 0; mt < 2; mt++)
        #pragma unroll
        for (int nt = 0; nt < 8; nt++)
            #pragma unroll
            for (int i = 0; i < 4; i++) acc[mt][nt][i] = 0.0f;

    const uint32 Ab0 = aBaseByte + (uint32)(mb + a_rl) * rowBytes;
    const uint32 Ab1 = Ab0 + 16u * rowBytes;
    const uint32 Bthread = (uint32)(nb + b_no + l7) * 128u;
    const bool bigA = (rowBytes == 512);

    if (!stage0_done){
        uint32 dst = smem_base + (SB_U + t*16)*4;
        const uint32* s = gimg + t*16;
        #pragma unroll
        for (int j = 0; j < 4; j++) cpa16(dst + j*16, s + j*4);
        cp_commit();
    }
    for (int c = 0; c < kchunks; c++){
        if (c + 1 < kchunks){
            uint32 dst = smem_base + (SB_U + ((c+1)&1)*8192 + t*16)*4;
            const uint32* s = gimg + (c+1)*8192 + t*16;
            #pragma unroll
            for (int j = 0; j < 4; j++) cpa16(dst + j*16, s + j*4);
            cp_commit();
            cp_wait<1>();
        } else {
            cp_wait<0>();
        }
        __syncthreads();
        uint32 sBcur = smem_base + (SB_U + (c&1)*8192)*4;
        #pragma unroll
        for (int ks = 0; ks < 4; ks++){
            uint32 ar[2][4];
            int qA = (bigA ? c*8 : 0) + ks*2 + a_qo;
            uint32 axor = (uint32)((qA ^ l7) << 4);
            ldsm4(ar[0], Ab0 + axor);
            ldsm4(ar[1], Ab1 + axor);
            uint32 bxor = (uint32)((((ks*2 + b_kh) ^ b_r7)) << 4);
            #pragma unroll
            for (int j = 0; j < 4; j++){
                uint32 br[4];
                ldsm4(br, sBcur + Bthread + (uint32)(j*16*128) + bxor);
                #pragma unroll
                for (int mt = 0; mt < 2; mt++){
                    mma16(acc[mt][2*j],     ar[mt], br[0], br[1]);
                    mma16(acc[mt][2*j + 1], ar[mt], br[2], br[3]);
                }
            }
        }
        __syncthreads();
    }
}

// epilogue: acc -> bf16 A-layout (bias + relu), dst row stride 128 words
static __device__ __forceinline__ void epi_big(
    float acc[2][8][4], const float* __restrict__ gb, uint32* __restrict__ dstU)
{
    const int t = threadIdx.x;
    const int lane = t & 31, w = t >> 5;
    const int wm = w >> 2, wn = w & 3;
    const int mb = wm*32, nb = wn*64;
    const int g = lane >> 2, tig = lane & 3;
    #pragma unroll
    for (int mt = 0; mt < 2; mt++){
        int r0 = mb + mt*16 + g, r1 = r0 + 8;
        #pragma unroll
        for (int nt = 0; nt < 8; nt++){
            int col = nb + nt*8 + 2*tig;
            float b0 = gb[col], b1 = gb[col+1];
            uint32 w0 = bpack(fmaxf(acc[mt][nt][0] + b0, 0.0f), fmaxf(acc[mt][nt][1] + b1, 0.0f));
            uint32 w1 = bpack(fmaxf(acc[mt][nt][2] + b0, 0.0f), fmaxf(acc[mt][nt][3] + b1, 0.0f));
            int p = wn*32 + nt*4 + tig;
            int phys = (((p>>2) ^ (g & 7)) << 2) | (p & 3);
            dstU[r0*128 + phys] = w0;
            dstU[r1*128 + phys] = w1;
        }
    }
}

// ---------------- small w2 GEMMs (A = h1 in sB region), warps 0..7 only ----------------
static __device__ __forceinline__ void gemm_w2_n8(
    float acc8[4], uint32 smem_base, int w2off_u)
{
    const int t = threadIdx.x;
    const int lane = t & 31, w = (t >> 5) & 7;
    const int mb = w*16;
    const int l7 = lane & 7, lm = lane >> 3;
    const int a_rl = l7 + ((lm & 1) << 3);
    const int a_qo = lm >> 1;
    const int b_kh2 = lm & 1;
    #pragma unroll
    for (int i = 0; i < 4; i++) acc8[i] = 0.0f;
    const uint32 Ab = smem_base + SB_U*4 + (uint32)(mb + a_rl)*512u;
    const uint32 Bb = smem_base + (SW2_U + w2off_u)*4 + (uint32)l7*128u;
    #pragma unroll
    for (int c = 0; c < 4; c++){
        #pragma unroll
        for (int ks = 0; ks < 4; ks++){
            uint32 ar[4];
            int qA = c*8 + ks*2 + a_qo;
            ldsm4(ar, Ab + (uint32)((qA ^ l7) << 4));
            uint32 br[2];
            ldsm2(br, Bb + (uint32)(c*1024) + (uint32)(((ks*2 + b_kh2) ^ l7) << 4));
            mma16(acc8, ar, br[0], br[1]);
        }
    }
}

static __device__ __forceinline__ void gemm_w2_n48(
    float acc48[6][4], uint32 smem_base, int w2off_u)
{
    const int t = threadIdx.x;
    const int lane = t & 31, w = (t >> 5) & 7;
    const int mb = w*16;
    const int l7 = lane & 7, lm = lane >> 3;
    const int a_rl = l7 + ((lm & 1) << 3);
    const int a_qo = lm >> 1;
    const int b_kh = lm & 1;
    const int b_no = (lm >> 1) << 3;
    const int b_r7 = (b_no + l7) & 7;
    #pragma unroll
    for (int nt = 0; nt < 6; nt++)
        #pragma unroll
        for (int i = 0; i < 4; i++) acc48[nt][i] = 0.0f;
    const uint32 Ab = smem_base + SB_U*4 + (uint32)(mb + a_rl)*512u;
    const uint32 Bb = smem_base + (SW2_U + w2off_u)*4 + (uint32)(b_no + l7)*128u;
    #pragma unroll
    for (int c = 0; c < 4; c++){
        #pragma unroll
        for (int ks = 0; ks < 4; ks++){
            uint32 ar[4];
            int qA = c*8 + ks*2 + a_qo;
            ldsm4(ar, Ab + (uint32)((qA ^ l7) << 4));
            uint32 bxor = (uint32)(((ks*2 + b_kh) ^ b_r7) << 4);
            #pragma unroll
            for (int ntp = 0; ntp < 3; ntp++){
                uint32 br[4];
                ldsm4(br, Bb + (uint32)(c*48*128) + (uint32)(ntp*16*128) + bxor);
                mma16(acc48[2*ntp],   ar, br[0], br[1]);
                mma16(acc48[2*ntp+1], ar, br[2], br[3]);
            }
        }
    }
}

// ---------------- phase A: K-planes bilinear sampling -> sF (bf16 A-layout) ----------------
static __device__ __forceinline__ void phaseA(
    const float* __restrict__ sp, const float* __restrict__ tp,
    const float* __restrict__ rays, const float* __restrict__ tim,
    const int* sidx, uint32* __restrict__ sF)
{
    const int t = threadIdx.x;
    const int pt = t >> 2, fg = t & 3;
    const int gi = sidx[pt];
    float px = rays[3*gi], py = rays[3*gi+1], pz = rays[3*gi+2];
    float tv = tim[gi];
    float cx = fminf(fmaxf((px*(1.0f/1.3f) + 1.0f)*0.5f, 0.0f), 1.0f) * 127.0f;
    float cy = fminf(fmaxf((py*(1.0f/1.3f) + 1.0f)*0.5f, 0.0f), 1.0f) * 127.0f;
    float cz = fminf(fmaxf((pz*(1.0f/1.3f) + 1.0f)*0.5f, 0.0f), 1.0f) * 127.0f;
    float tq = fminf(fmaxf(tv, 0.0f), 1.0f) * 63.0f;

    const float* PB[6];
    int O00[6], O10[6], O01[6], O11[6];
    float W00[6], W10[6], W01[6], W11[6];

#define SETP(s, bp, R2, uu, vv) { \
    float u_ = fminf(fmaxf((uu), 0.0f), 127.0f); \
    float v_ = fminf(fmaxf((vv), 0.0f), (float)((R2)-1)); \
    int i0 = (int)u_; int j0 = (int)v_; \
    int i1 = min(i0+1, 127); int j1 = min(j0+1, (R2)-1); \
    float fu = u_ - (float)i0, fv = v_ - (float)j0; \
    PB[s] = (bp); \
    O00[s] = (i0*(R2)+j0)*64; O10[s] = (i1*(R2)+j0)*64; \
    O01[s] = (i0*(R2)+j1)*64; O11[s] = (i1*(R2)+j1)*64; \
    W00[s] = (1.0f-fu)*(1.0f-fv); W10[s] = fu*(1.0f-fv); \
    W01[s] = (1.0f-fu)*fv;        W11[s] = fu*fv; }

    SETP(0, sp,           128, cx, cy)
    SETP(1, sp + 1048576, 128, cx, cz)
    SETP(2, sp + 2097152, 128, cy, cz)
    SETP(3, tp,            64, cx, tq)
    SETP(4, tp + 524288,   64, cy, tq)
    SETP(5, tp + 1048576,  64, cz, tq)
#undef SETP

    #pragma unroll
    for (int q = 0; q < 4; q++){
        int f = fg*16 + q*4;
        float r0 = 1.0f, r1 = 1.0f, r2 = 1.0f, r3 = 1.0f;
        #pragma unroll
        for (int s = 0; s < 6; s++){
            const float* b = PB[s] + f;
            float4 v00 = *(const float4*)(b + O00[s]);
            float4 v10 = *(const float4*)(b + O10[s]);
            float4 v01 = *(const float4*)(b + O01[s]);
            float4 v11 = *(const float4*)(b + O11[s]);
            float sx = v00.x*W00[s] + v10.x*W10[s] + v01.x*W01[s] + v11.x*W11[s];
            float sy = v00.y*W00[s] + v10.y*W10[s] + v01.y*W01[s] + v11.y*W11[s];
            float sz = v00.z*W00[s] + v10.z*W10[s] + v01.z*W01[s] + v11.z*W11[s];
            float sw_ = v00.w*W00[s] + v10.w*W10[s] + v01.w*W01[s] + v11.w*W11[s];
            r0 *= sx; r1 *= sy; r2 *= sz; r3 *= sw_;
        }
        int p0 = fg*8 + q*2;
        int phys0 = (((p0>>2) ^ (pt & 7)) << 2) | (p0 & 3);
        int p1 = p0 + 1;
        int phys1 = (((p1>>2) ^ (pt & 7)) << 2) | (p1 & 3);
        sF[pt*32 + phys0] = bpack(r0, r1);
        sF[pt*32 + phys1] = bpack(r2, r3);
    }
}

// ---------------- main kernel ----------------
__global__ void __launch_bounds__(512, 1) main_kernel(
    const float* __restrict__ rays, const float* __restrict__ rot_emb,
    const float* __restrict__ shs_emb, const float* __restrict__ tim,
    const float* __restrict__ tgt_sp, const float* __restrict__ tgt_tp,
    const float* __restrict__ bg_sp,  const float* __restrict__ bg_tp,
    const float* __restrict__ st_b,   const float* __restrict__ bg_st_b,
    const float* __restrict__ pos_b1, const float* __restrict__ pos_b2,
    const float* __restrict__ bgpos_b1, const float* __restrict__ bgpos_b2,
    const float* __restrict__ rot_b1, const float* __restrict__ rot_b2,
    const float* __restrict__ shs_b1, const float* __restrict__ shs_b2,
    float* __restrict__ out, int n)
{
    extern __shared__ uint32 smu[];
    const uint32 smem_base = (uint32)__cvta_generic_to_shared(smu);
    __shared__ int sidx[128];
    __shared__ int s_meta[3];

    const int t = threadIdx.x;
    if (t == 0){
        int mc = g_cnt_m;
        int mtiles = (mc + 127) >> 7;
        int bid = blockIdx.x;
        int seg, start, cnt;
        if (bid < mtiles){ seg = 0; start = bid << 7; cnt = min(128, mc - start); }
        else {
            int uc = n - mc;
            start = (bid - mtiles) << 7;
            seg = 1;
            cnt = (start < uc) ? min(128, uc - start) : 0;
        }
        s_meta[0] = seg; s_meta[1] = cnt; s_meta[2] = start;
    }
    __syncthreads();
    const int cnt = s_meta[1];
    if (cnt <= 0) return;
    const int seg = s_meta[0], start = s_meta[2];
    if (t < 128){
        int j = (t < cnt) ? t : 0;
        sidx[t] = (seg == 0) ? g_idx[start + j] : g_idx[n - 1 - (start + j)];
    }
    __syncthreads();

    // prologue staging: stem chunk -> sB buf0, w2 images -> sW2
    {
        const uint32* stem_img = g_wimg + (seg ? IMG_BGST : IMG_ST);
        uint32 dst = smem_base + (SB_U + t*16)*4;
        const uint32* s = stem_img + t*16;
        #pragma unroll
        for (int j = 0; j < 4; j++) cpa16(dst + j*16, s + j*4);
        if (seg == 0){
            uint32 d2 = smem_base + (SW2_U + t*16)*4;
            const uint32* s2 = g_wimg + IMG_POSW2 + t*16;
            #pragma unroll
            for (int j = 0; j < 4; j++) cpa16(d2 + j*16, s2 + j*4);
        } else {
            if (t < 256) cpa16(smem_base + (SW2_U + t*4)*4, g_wimg + IMG_BGPOSW2 + t*4);
        }
        cp_commit();
    }

    phaseA(seg ? bg_sp : tgt_sp, seg ? bg_tp : tgt_tp, rays, tim, sidx, smu + SF_U);
    cp_wait<0>();
    __syncthreads();

    float acc[2][8][4];

    // stem: h = relu(feat @ st_w + b) -> sA
    gemm_big(acc, g_wimg, smem_base, smem_base + SF_U*4, 128, 1, true);
    epi_big(acc, seg ? bg_st_b : st_b, smu + SA_U);
    __syncthreads();

    const int lane = t & 31, w = t >> 5;
    const int g = lane >> 2, tig = lane & 3;
    const int mb2 = (w & 7)*16;

    if (seg == 0){
        // ---- pos head ----
        gemm_big(acc, g_wimg + IMG_POSW1, smem_base, smem_base + SA_U*4, 512, 4, false);
        epi_big(acc, pos_b1, smu + SB_U);
        __syncthreads();
        if (w < 8){
            float a8[4];
            gemm_w2_n8(a8, smem_base, 0);
            #pragma unroll
            for (int i = 0; i < 2; i++){
                int pt = mb2 + g + 8*i;
                int gi = sidx[pt];
                #pragma unroll
                for (int jj = 0; jj < 2; jj++){
                    int col = 2*tig + jj;
                    if (col < 3){
                        float d = a8[i*2+jj] + pos_b2[col];
                        out[(size_t)gi*3 + col] = rays[gi*3 + col] + d;
                    }
                }
            }
        }
        __syncthreads();
        // ---- rot head ----
        gemm_big(acc, g_wimg + IMG_ROTW1, smem_base, smem_base + SA_U*4, 512, 4, false);
        epi_big(acc, rot_b1, smu + SB_U);
        __syncthreads();
        if (w < 8){
            float a8[4];
            gemm_w2_n8(a8, smem_base, 1024);
            #pragma unroll
            for (int i = 0; i < 2; i++){
                int pt = mb2 + g + 8*i;
                int gi = sidx[pt];
                #pragma unroll
                for (int jj = 0; jj < 2; jj++){
                    int col = 2*tig + jj;
                    if (col < 4){
                        float d = a8[i*2+jj] + rot_b2[col];
                        out[(size_t)3*n + (size_t)gi*4 + col] = rot_emb[(size_t)gi*4 + col] + d;
                    }
                }
            }
        }
        __syncthreads();
        // ---- shs head ----
        gemm_big(acc, g_wimg + IMG_SHSW1, smem_base, smem_base + SA_U*4, 512, 4, false);
        epi_big(acc, shs_b1, smu + SB_U);
        __syncthreads();
        if (w < 8){
            float a48[6][4];
            gemm_w2_n48(a48, smem_base, 2048);
            float* o8 = out + (size_t)8*n;
            #pragma unroll
            for (int i = 0; i < 2; i++){
                int pt = mb2 + g + 8*i;
                int gi = sidx[pt];
                const float* se = shs_emb + (size_t)gi*48;
                float* od = o8 + (size_t)gi*48;
                #pragma unroll
                for (int nt = 0; nt < 6; nt++){
                    #pragma unroll
                    for (int jj = 0; jj < 2; jj++){
                        int col = nt*8 + 2*tig + jj;
                        float d = a48[nt][i*2+jj] + shs_b2[col];
                        od[col] = se[col] + d;
                    }
                }
            }
        }
    } else {
        // ---- bgpos head ----
        gemm_big(acc, g_wimg + IMG_BGPOSW1, smem_base, smem_base + SA_U*4, 512, 4, false);
        epi_big(acc, bgpos_b1, smu + SB_U);
        __syncthreads();
        if (w < 8){
            float a8[4];
            gemm_w2_n8(a8, smem_base, 0);
            #pragma unroll
            for (int i = 0; i < 2; i++){
                int pt = mb2 + g + 8*i;
                int gi = sidx[pt];
                #pragma unroll
                for (int jj = 0; jj < 2; jj++){
                    int col = 2*tig + jj;
                    if (col < 3){
                        float d = a8[i*2+jj] + bgpos_b2[col];
                        out[(size_t)gi*3 + col] = rays[gi*3 + col] + d;
                    }
                }
            }
        }
    }
}

extern "C" void kernel_launch(void* const* d_in, const int* in_sizes, int n_in,
                              void* d_out, int out_size) {
    const float* rays    = (const float*)d_in[0];
    const float* rot_emb = (const float*)d_in[1];
    const float* shs_emb = (const float*)d_in[3];
    const float* tim     = (const float*)d_in[5];
    const float* h_emb   = (const float*)d_in[6];
    const void*  mask    = d_in[7];
    const float* tgt_sp  = (const float*)d_in[8];
    const float* tgt_tp  = (const float*)d_in[9];
    const float* bg_sp   = (const float*)d_in[10];
    const float* bg_tp   = (const float*)d_in[11];
    const float* st_w    = (const float*)d_in[12];
    const float* st_b    = (const float*)d_in[13];
    const float* bg_st_w = (const float*)d_in[14];
    const float* bg_st_b = (const float*)d_in[15];
    const float* pos_w1  = (const float*)d_in[16];
    const float* pos_b1  = (const float*)d_in[17];
    const float* pos_w2  = (const float*)d_in[18];
    const float* pos_b2  = (const float*)d_in[19];
    const float* bgpos_w1= (const float*)d_in[20];
    const float* bgpos_b1= (const float*)d_in[21];
    const float* bgpos_w2= (const float*)d_in[22];
    const float* bgpos_b2= (const float*)d_in[23];
    const float* rot_w1  = (const float*)d_in[24];
    const float* rot_b1  = (const float*)d_in[25];
    const float* rot_w2  = (const float*)d_in[26];
    const float* rot_b2  = (const float*)d_in[27];
    const float* shs_w1  = (const float*)d_in[28];
    const float* shs_b1  = (const float*)d_in[29];
    const float* shs_w2  = (const float*)d_in[30];
    const float* shs_b2  = (const float*)d_in[31];
    float* out = (float*)d_out;
    int n = in_sizes[0] / 3;

    cudaFuncSetAttribute(main_kernel, cudaFuncAttributeMaxDynamicSharedMemorySize, SMEM_BYTES);

    convert_kernel<<<(IMG_TOTAL + 255)/256, 256>>>(
        st_w, bg_st_w, pos_w1, bgpos_w1, rot_w1, shs_w1,
        pos_w2, rot_w2, shs_w2, bgpos_w2);
    setup_kernel<<<1, 256>>>((const unsigned char*)mask);
    elem_kernel<<<(n + 255)/256, 256>>>(rot_emb, shs_emb, tim, h_emb, mask, out, n);
    int nb = (n + 127)/128 + 1;
    main_kernel<<<nb, 512, SMEM_BYTES>>>(
        rays, rot_emb, shs_emb, tim,
        tgt_sp, tgt_tp, bg_sp, bg_tp,
        st_b, bg_st_b,
        pos_b1, pos_b2, bgpos_b1, bgpos_b2,
        rot_b1, rot_b2, shs_b1, shs_b2,
        out, n);
}

// round 6
// speedup vs baseline: 6.6412x; 1.3024x over previous
#include <cuda_runtime.h>
#include <cuda_bf16.h>
#include <math.h>

#define NMAX 400000
typedef unsigned int uint32;

__device__ int g_cnt_m;
__device__ int g_cnt_u;
__device__ int g_mask_mode;
__device__ int g_idx[NMAX];

// ---------------- bf16-packed plane image (pairs of features per word) ----------------
#define P_TGT_SP 0
#define P_TGT_TP 1572864
#define P_BG_SP  2359296
#define P_BG_TP  3932160
#define P_TOTAL  4718592
__device__ uint32 g_planes[P_TOTAL];

// ---------------- weight image (bf16, pre-swizzled, chunk-major) ----------------
#define IMG_ST       0
#define IMG_BGST     8192
#define IMG_POSW1    16384
#define IMG_BGPOSW1  49152
#define IMG_ROTW1    81920
#define IMG_SHSW1    114688
#define IMG_POSW2    147456
#define IMG_ROTW2    148480
#define IMG_SHSW2    149504
#define IMG_BGPOSW2  155648
#define IMG_TOTAL    156672
__device__ uint32 g_wimg[IMG_TOTAL];

// ---------------- smem layout (u32 units) ----------------
#define SF_U   0          // feat: 128 rows x 32 words
#define SA_U   4096       // h:    128 rows x 128 words
#define SB_U   20480      // weight chunks 2 x 8192 / h1: 128 x 128 words
#define SW2_U  36864      // w2 frag images: up to 8192 words
#define TOTAL_U 45056
#define SMEM_BYTES (TOTAL_U*4)

// ---------------- helpers ----------------
static __device__ __forceinline__ float sigm(float x){ return 1.0f/(1.0f+expf(-x)); }
static __device__ __forceinline__ uint32 bpack(float a, float b){
    __nv_bfloat162 h = __float22bfloat162_rn(make_float2(a,b));
    return *reinterpret_cast<uint32*>(&h);
}
static __device__ __forceinline__ float2 bf2f(uint32 w){
    __nv_bfloat162 h;
    *reinterpret_cast<uint32*>(&h) = w;
    return __bfloat1622float2(h);
}
static __device__ __forceinline__ void ldsm4(uint32* r, uint32 addr){
    asm volatile("ldmatrix.sync.aligned.m8n8.x4.shared.b16 {%0,%1,%2,%3},[%4];"
      : "=r"(r[0]),"=r"(r[1]),"=r"(r[2]),"=r"(r[3]) : "r"(addr));
}
static __device__ __forceinline__ void mma16(float* d, const uint32* a, uint32 b0, uint32 b1){
    asm volatile("mma.sync.aligned.m16n8k16.row.col.f32.bf16.bf16.f32 "
      "{%0,%1,%2,%3},{%4,%5,%6,%7},{%8,%9},{%0,%1,%2,%3};"
      : "+f"(d[0]),"+f"(d[1]),"+f"(d[2]),"+f"(d[3])
      : "r"(a[0]),"r"(a[1]),"r"(a[2]),"r"(a[3]),"r"(b0),"r"(b1));
}
static __device__ __forceinline__ void cpa16(uint32 saddr, const void* g){
    asm volatile("cp.async.cg.shared.global [%0],[%1],16;" :: "r"(saddr), "l"(g));
}
static __device__ __forceinline__ void cp_commit(){ asm volatile("cp.async.commit_group;"); }
template<int N> static __device__ __forceinline__ void cp_wait(){ asm volatile("cp.async.wait_group %0;"::"n"(N)); }

// ---------------- convert planes: f32 -> packed bf16 pairs ----------------
__global__ void convert_planes(const float* __restrict__ tsp, const float* __restrict__ ttp,
                               const float* __restrict__ bsp, const float* __restrict__ btp){
    int i = blockIdx.x*blockDim.x + threadIdx.x;
    if (i >= P_TOTAL) return;
    const float* src; int off;
    if      (i < P_TGT_TP){ src = tsp; off = i; }
    else if (i < P_BG_SP) { src = ttp; off = i - P_TGT_TP; }
    else if (i < P_BG_TP) { src = bsp; off = i - P_BG_SP; }
    else                  { src = btp; off = i - P_BG_TP; }
    g_planes[i] = bpack(src[2*off], src[2*off+1]);
}

// ---------------- convert weights: f32 -> swizzled bf16 W1 images + w2 frag images ----------------
__global__ void convert_kernel(const float* st_w, const float* bg_st_w,
    const float* pos_w1, const float* bgpos_w1, const float* rot_w1, const float* shs_w1,
    const float* pos_w2, const float* rot_w2, const float* shs_w2, const float* bgpos_w2)
{
    int i = blockIdx.x*blockDim.x + threadIdx.x;
    if (i >= IMG_TOTAL) return;
    if (i < IMG_POSW2){
        const float* src; int base;
        if      (i < IMG_BGST)   { src=st_w;    base=IMG_ST; }
        else if (i < IMG_POSW1)  { src=bg_st_w; base=IMG_BGST; }
        else if (i < IMG_BGPOSW1){ src=pos_w1;  base=IMG_POSW1; }
        else if (i < IMG_ROTW1)  { src=bgpos_w1;base=IMG_BGPOSW1; }
        else if (i < IMG_SHSW1)  { src=rot_w1;  base=IMG_ROTW1; }
        else                     { src=shs_w1;  base=IMG_SHSW1; }
        int wi = i - base;
        int wpc = 256*32;
        int chunk = wi / wpc, r = wi % wpc;
        int nrow = r >> 5, pw = r & 31;
        int q = (pw>>2) ^ (nrow&7);
        int p = (q<<2) | (pw&3);
        int k = chunk*64 + 2*p;
        g_wimg[i] = bpack(src[(size_t)k*256 + nrow], src[(size_t)(k+1)*256 + nrow]);
    } else {
        // w2 fragment images: word = ((kc*NT + nt)*2 + h)*32 + lane
        const float* src; int N, NT, base;
        if      (i < IMG_ROTW2)  { src=pos_w2;  N=3;  NT=1; base=IMG_POSW2; }
        else if (i < IMG_SHSW2)  { src=rot_w2;  N=4;  NT=1; base=IMG_ROTW2; }
        else if (i < IMG_BGPOSW2){ src=shs_w2;  N=48; NT=6; base=IMG_SHSW2; }
        else                     { src=bgpos_w2;N=3;  NT=1; base=IMG_BGPOSW2; }
        int wi = i - base;
        int lane = wi & 31;
        int tmp = wi >> 5;
        int h = tmp & 1;
        int tmp2 = tmp >> 1;
        int nt = tmp2 % NT;
        int kc = tmp2 / NT;
        int g = lane >> 2, tig = lane & 3;
        int k0 = kc*16 + 2*tig + 8*h;
        int col = nt*8 + g;
        float lo = 0.0f, hi = 0.0f;
        if (col < N){ lo = src[(size_t)k0*N + col]; hi = src[(size_t)(k0+1)*N + col]; }
        g_wimg[i] = bpack(lo, hi);
    }
}

// ---------------- setup: mask dtype sniff + counter reset ----------------
__global__ void setup_kernel(const unsigned char* __restrict__ mb){
    __shared__ int s3f, s3f1, s1off;
    if (threadIdx.x == 0){ s3f = 0; s3f1 = 0; s1off = 0; }
    __syncthreads();
    int a = 0, b = 0, c = 0;
    for (int i = threadIdx.x; i < 4096; i += blockDim.x){
        unsigned v = mb[i];
        if (v == 0x3fu){ a = 1; if ((i & 3) == 1) b = 1; }
        if (v == 0x01u && (i & 3) != 0) c = 1;
    }
    if (a) atomicOr(&s3f, 1);
    if (b) atomicOr(&s3f1, 1);
    if (c) atomicOr(&s1off, 1);
    __syncthreads();
    if (threadIdx.x == 0){
        int mode;
        if (s3f) mode = s3f1 ? 3 : 2;
        else     mode = s1off ? 0 : 1;
        g_mask_mode = mode;
        g_cnt_m = 0;
        g_cnt_u = 0;
    }
}

static __device__ __forceinline__ bool read_mask(const void* m, int i, int mode){
    if (mode == 0) return ((const unsigned char*)m)[i] != 0;
    if (mode == 1) return ((const int*)m)[i] != 0;
    if (mode == 2) return ((const float*)m)[i] != 0.0f;
    return ((const unsigned short*)m)[i] != 0;
}

// ---------------- elementwise: opacity, passthroughs, mask partition ----------------
__global__ void elem_kernel(const float* __restrict__ rot_emb, const float* __restrict__ shs_emb,
                            const float* __restrict__ tim, const float* __restrict__ h_emb,
                            const void* __restrict__ mask, float* __restrict__ out, int n){
    __shared__ int sm_m, sm_u, base_m, base_u;
    if (threadIdx.x == 0){ sm_m = 0; sm_u = 0; }
    __syncthreads();
    int i = blockIdx.x*blockDim.x + threadIdx.x;
    bool valid = (i < n);
    int mode = g_mask_mode;
    bool msk = false;
    int pos = 0;
    if (valid){
        msk = read_mask(mask, i, mode);
        pos = msk ? atomicAdd(&sm_m, 1) : atomicAdd(&sm_u, 1);
    }
    __syncthreads();
    if (threadIdx.x == 0){
        base_m = atomicAdd(&g_cnt_m, sm_m);
        base_u = atomicAdd(&g_cnt_u, sm_u);
    }
    __syncthreads();
    if (!valid) return;
    float t0 = tim[0];
    float he0 = h_emb[3*i], he1 = h_emb[3*i+1], he2 = h_emb[3*i+2];
    float op;
    if (msk){
        float mu = sigm(he2);
        float w  = he1*he1;
        float d  = t0 - mu;
        op = expf(-w*d*d);
    } else {
        op = sigm(he0);
    }
    out[(size_t)7*n + i] = op;
    if (msk){
        g_idx[base_m + pos] = i;
    } else {
        g_idx[n - 1 - (base_u + pos)] = i;
        ((float4*)(out + (size_t)3*n))[i] = ((const float4*)rot_emb)[i];
        const float4* s4 = (const float4*)shs_emb + (size_t)i*12;
        float4* d4 = (float4*)(out + (size_t)8*n) + (size_t)i*12;
        #pragma unroll
        for (int q = 0; q < 12; q++) d4[q] = s4[q];
    }
}

// ---------------- prefetch chunk0 of a W1 image into sB buf0 ----------------
static __device__ __forceinline__ void prefetch_chunk0(uint32 smem_base, const uint32* gimg){
    const int t = threadIdx.x;
    uint32 dst = smem_base + (SB_U + t*16)*4;
    const uint32* s = gimg + t*16;
    #pragma unroll
    for (int j = 0; j < 4; j++) cpa16(dst + j*16, s + j*4);
    cp_commit();
}

// ---------------- big GEMM: 128x256, 16 warps (4m x 4n), A bf16 swizzled in smem ----------------
static __device__ __forceinline__ void gemm_big(
    float acc[2][8][4], const uint32* gimg, uint32 smem_base,
    uint32 aBaseByte, int rowBytes, int kchunks)
{
    const int t = threadIdx.x;
    const int lane = t & 31, w = t >> 5;
    const int wm = w >> 2, wn = w & 3;
    const int mb = wm*32, nb = wn*64;
    const int l7 = lane & 7, lm = lane >> 3;
    const int a_rl = l7 + ((lm & 1) << 3);
    const int a_qo = lm >> 1;
    const int b_kh = lm & 1;
    const int b_no = (lm >> 1) << 3;
    const int b_r7 = (b_no + l7) & 7;

    #pragma unroll
    for (int mt = 0; mt < 2; mt++)
        #pragma unroll
        for (int nt = 0; nt < 8; nt++)
            #pragma unroll
            for (int i = 0; i < 4; i++) acc[mt][nt][i] = 0.0f;

    const uint32 Ab0 = aBaseByte + (uint32)(mb + a_rl) * rowBytes;
    const uint32 Ab1 = Ab0 + 16u * rowBytes;
    const uint32 Bthread = (uint32)(nb + b_no + l7) * 128u;
    const bool bigA = (rowBytes == 512);

    for (int c = 0; c < kchunks; c++){
        if (c + 1 < kchunks){
            uint32 dst = smem_base + (SB_U + ((c+1)&1)*8192 + t*16)*4;
            const uint32* s = gimg + (c+1)*8192 + t*16;
            #pragma unroll
            for (int j = 0; j < 4; j++) cpa16(dst + j*16, s + j*4);
            cp_commit();
            cp_wait<1>();
        } else {
            cp_wait<0>();
        }
        __syncthreads();
        uint32 sBcur = smem_base + (SB_U + (c&1)*8192)*4;
        #pragma unroll
        for (int ks = 0; ks < 4; ks++){
            uint32 ar[2][4];
            int qA = (bigA ? c*8 : 0) + ks*2 + a_qo;
            uint32 axor = (uint32)((qA ^ l7) << 4);
            ldsm4(ar[0], Ab0 + axor);
            ldsm4(ar[1], Ab1 + axor);
            uint32 bxor = (uint32)((((ks*2 + b_kh) ^ b_r7)) << 4);
            #pragma unroll
            for (int j = 0; j < 4; j++){
                uint32 br[4];
                ldsm4(br, sBcur + Bthread + (uint32)(j*16*128) + bxor);
                #pragma unroll
                for (int mt = 0; mt < 2; mt++){
                    mma16(acc[mt][2*j],     ar[mt], br[0], br[1]);
                    mma16(acc[mt][2*j + 1], ar[mt], br[2], br[3]);
                }
            }
        }
        __syncthreads();
    }
}

// epilogue: acc -> bf16 A-layout (bias + relu), dst row stride 128 words
static __device__ __forceinline__ void epi_big(
    float acc[2][8][4], const float* __restrict__ gb, uint32* __restrict__ dstU)
{
    const int t = threadIdx.x;
    const int lane = t & 31, w = t >> 5;
    const int wm = w >> 2, wn = w & 3;
    const int mb = wm*32, nb = wn*64;
    const int g = lane >> 2, tig = lane & 3;
    #pragma unroll
    for (int mt = 0; mt < 2; mt++){
        int r0 = mb + mt*16 + g, r1 = r0 + 8;
        #pragma unroll
        for (int nt = 0; nt < 8; nt++){
            int col = nb + nt*8 + 2*tig;
            float b0 = gb[col], b1 = gb[col+1];
            uint32 w0 = bpack(fmaxf(acc[mt][nt][0] + b0, 0.0f), fmaxf(acc[mt][nt][1] + b1, 0.0f));
            uint32 w1 = bpack(fmaxf(acc[mt][nt][2] + b0, 0.0f), fmaxf(acc[mt][nt][3] + b1, 0.0f));
            int p = wn*32 + nt*4 + tig;
            int phys = (((p>>2) ^ (g & 7)) << 2) | (p & 3);
            dstU[r0*128 + phys] = w0;
            dstU[r1*128 + phys] = w1;
        }
    }
}

// ---------------- small w2 GEMMs (A = h1 in sB region, B = frag image in sW2), warps 0..7 ----------------
static __device__ __forceinline__ void gemm_w2_n8(
    float acc8[4], uint32 smem_base, const uint32* __restrict__ smu, int w2off_u)
{
    const int t = threadIdx.x;
    const int lane = t & 31, w = (t >> 5) & 7;
    const int mb = w*16;
    const int l7 = lane & 7, lm = lane >> 3;
    const int a_rl = l7 + ((lm & 1) << 3);
    const int a_qo = lm >> 1;
    #pragma unroll
    for (int i = 0; i < 4; i++) acc8[i] = 0.0f;
    const uint32 Ab = smem_base + SB_U*4 + (uint32)(mb + a_rl)*512u;
    const uint32* wp = smu + SW2_U + w2off_u;
    #pragma unroll
    for (int kc = 0; kc < 16; kc++){
        uint32 ar[4];
        int qA = kc*2 + a_qo;
        ldsm4(ar, Ab + (uint32)((qA ^ l7) << 4));
        uint32 b0 = wp[(kc*2 + 0)*32 + lane];
        uint32 b1 = wp[(kc*2 + 1)*32 + lane];
        mma16(acc8, ar, b0, b1);
    }
}

static __device__ __forceinline__ void gemm_w2_n48(
    float acc48[6][4], uint32 smem_base, const uint32* __restrict__ smu, int w2off_u)
{
    const int t = threadIdx.x;
    const int lane = t & 31, w = (t >> 5) & 7;
    const int mb = w*16;
    const int l7 = lane & 7, lm = lane >> 3;
    const int a_rl = l7 + ((lm & 1) << 3);
    const int a_qo = lm >> 1;
    #pragma unroll
    for (int nt = 0; nt < 6; nt++)
        #pragma unroll
        for (int i = 0; i < 4; i++) acc48[nt][i] = 0.0f;
    const uint32 Ab = smem_base + SB_U*4 + (uint32)(mb + a_rl)*512u;
    const uint32* wp = smu + SW2_U + w2off_u;
    #pragma unroll 4
    for (int kc = 0; kc < 16; kc++){
        uint32 ar[4];
        int qA = kc*2 + a_qo;
        ldsm4(ar, Ab + (uint32)((qA ^ l7) << 4));
        #pragma unroll
        for (int nt = 0; nt < 6; nt++){
            uint32 b0 = wp[((kc*6 + nt)*2 + 0)*32 + lane];
            uint32 b1 = wp[((kc*6 + nt)*2 + 1)*32 + lane];
            mma16(acc48[nt], ar, b0, b1);
        }
    }
}

// ---------------- phase A: K-planes bilinear sampling from bf16 image -> sF ----------------
static __device__ __forceinline__ void phaseA(
    int seg, const float* __restrict__ rays, const float* __restrict__ tim,
    const int* sidx, uint32* __restrict__ sF)
{
    const int t = threadIdx.x;
    const int pt = t >> 2, fg = t & 3;
    const int gi = sidx[pt];
    float px = rays[3*gi], py = rays[3*gi+1], pz = rays[3*gi+2];
    float tv = tim[gi];
    float cx = fminf(fmaxf((px*(1.0f/1.3f) + 1.0f)*0.5f, 0.0f), 1.0f) * 127.0f;
    float cy = fminf(fmaxf((py*(1.0f/1.3f) + 1.0f)*0.5f, 0.0f), 1.0f) * 127.0f;
    float cz = fminf(fmaxf((pz*(1.0f/1.3f) + 1.0f)*0.5f, 0.0f), 1.0f) * 127.0f;
    float tq = fminf(fmaxf(tv, 0.0f), 1.0f) * 63.0f;

    const uint32* sp = g_planes + (seg ? P_BG_SP : P_TGT_SP);
    const uint32* tp = g_planes + (seg ? P_BG_TP : P_TGT_TP);

    const uint32* PB[6];
    int O00[6], O10[6], O01[6], O11[6];
    float W00[6], W10[6], W01[6], W11[6];

#define SETP(s, bp, R2, uu, vv) { \
    float u_ = fminf(fmaxf((uu), 0.0f), 127.0f); \
    float v_ = fminf(fmaxf((vv), 0.0f), (float)((R2)-1)); \
    int i0 = (int)u_; int j0 = (int)v_; \
    int i1 = min(i0+1, 127); int j1 = min(j0+1, (R2)-1); \
    float fu = u_ - (float)i0, fv = v_ - (float)j0; \
    PB[s] = (bp); \
    O00[s] = (i0*(R2)+j0)*32; O10[s] = (i1*(R2)+j0)*32; \
    O01[s] = (i0*(R2)+j1)*32; O11[s] = (i1*(R2)+j1)*32; \
    W00[s] = (1.0f-fu)*(1.0f-fv); W10[s] = fu*(1.0f-fv); \
    W01[s] = (1.0f-fu)*fv;        W11[s] = fu*fv; }

    SETP(0, sp,          128, cx, cy)
    SETP(1, sp + 524288, 128, cx, cz)
    SETP(2, sp + 1048576,128, cy, cz)
    SETP(3, tp,           64, cx, tq)
    SETP(4, tp + 262144,  64, cy, tq)
    SETP(5, tp + 524288,  64, cz, tq)
#undef SETP

    #pragma unroll
    for (int h = 0; h < 2; h++){
        int foff = fg*8 + h*4;
        float r[8];
        #pragma unroll
        for (int j = 0; j < 8; j++) r[j] = 1.0f;
        #pragma unroll
        for (int s = 0; s < 6; s++){
            const uint32* bp = PB[s] + foff;
            uint4 u00 = *(const uint4*)(bp + O00[s]);
            uint4 u10 = *(const uint4*)(bp + O10[s]);
            uint4 u01 = *(const uint4*)(bp + O01[s]);
            uint4 u11 = *(const uint4*)(bp + O11[s]);
            const uint32* a0 = (const uint32*)&u00;
            const uint32* a1 = (const uint32*)&u10;
            const uint32* a2 = (const uint32*)&u01;
            const uint32* a3 = (const uint32*)&u11;
            #pragma unroll
            for (int wd = 0; wd < 4; wd++){
                float2 c00 = bf2f(a0[wd]);
                float2 c10 = bf2f(a1[wd]);
                float2 c01 = bf2f(a2[wd]);
                float2 c11 = bf2f(a3[wd]);
                float sx = c00.x*W00[s] + c10.x*W10[s] + c01.x*W01[s] + c11.x*W11[s];
                float sy = c00.y*W00[s] + c10.y*W10[s] + c01.y*W01[s] + c11.y*W11[s];
                r[2*wd]   *= sx;
                r[2*wd+1] *= sy;
            }
        }
        #pragma unroll
        for (int j = 0; j < 4; j++){
            int p = foff + j;
            int phys = (((p>>2) ^ (pt & 7)) << 2) | (p & 3);
            sF[pt*32 + phys] = bpack(r[2*j], r[2*j+1]);
        }
    }
}

// ---------------- main kernel ----------------
__global__ void __launch_bounds__(512, 1) main_kernel(
    const float* __restrict__ rays, const float* __restrict__ rot_emb,
    const float* __restrict__ shs_emb, const float* __restrict__ tim,
    const float* __restrict__ st_b,   const float* __restrict__ bg_st_b,
    const float* __restrict__ pos_b1, const float* __restrict__ pos_b2,
    const float* __restrict__ bgpos_b1, const float* __restrict__ bgpos_b2,
    const float* __restrict__ rot_b1, const float* __restrict__ rot_b2,
    const float* __restrict__ shs_b1, const float* __restrict__ shs_b2,
    float* __restrict__ out, int n)
{
    extern __shared__ uint32 smu[];
    const uint32 smem_base = (uint32)__cvta_generic_to_shared(smu);
    __shared__ int sidx[128];
    __shared__ int s_meta[3];

    const int t = threadIdx.x;
    if (t == 0){
        int mc = g_cnt_m;
        int mtiles = (mc + 127) >> 7;
        int bid = blockIdx.x;
        int seg, start, cnt;
        if (bid < mtiles){ seg = 0; start = bid << 7; cnt = min(128, mc - start); }
        else {
            int uc = n - mc;
            start = (bid - mtiles) << 7;
            seg = 1;
            cnt = (start < uc) ? min(128, uc - start) : 0;
        }
        s_meta[0] = seg; s_meta[1] = cnt; s_meta[2] = start;
    }
    __syncthreads();
    const int cnt = s_meta[1];
    if (cnt <= 0) return;
    const int seg = s_meta[0], start = s_meta[2];
    if (t < 128){
        int j = (t < cnt) ? t : 0;
        sidx[t] = (seg == 0) ? g_idx[start + j] : g_idx[n - 1 - (start + j)];
    }
    __syncthreads();

    // prologue staging: stem chunk -> sB buf0, w2 frag images -> sW2
    {
        const uint32* stem_img = g_wimg + (seg ? IMG_BGST : IMG_ST);
        uint32 dst = smem_base + (SB_U + t*16)*4;
        const uint32* s = stem_img + t*16;
        #pragma unroll
        for (int j = 0; j < 4; j++) cpa16(dst + j*16, s + j*4);
        if (seg == 0){
            uint32 d2 = smem_base + (SW2_U + t*16)*4;
            const uint32* s2 = g_wimg + IMG_POSW2 + t*16;
            #pragma unroll
            for (int j = 0; j < 4; j++) cpa16(d2 + j*16, s2 + j*4);
        } else {
            if (t < 256) cpa16(smem_base + (SW2_U + t*4)*4, g_wimg + IMG_BGPOSW2 + t*4);
        }
        cp_commit();
    }

    phaseA(seg, rays, tim, sidx, smu + SF_U);
    cp_wait<0>();
    __syncthreads();

    float acc[2][8][4];

    // stem: h = relu(feat @ st_w + b) -> sA
    gemm_big(acc, g_wimg + (seg ? IMG_BGST : IMG_ST), smem_base, smem_base + SF_U*4, 128, 1);
    // prefetch first head's chunk0 into buf0 (sB is free; epi writes sA)
    prefetch_chunk0(smem_base, g_wimg + (seg ? IMG_BGPOSW1 : IMG_POSW1));
    epi_big(acc, seg ? bg_st_b : st_b, smu + SA_U);

    const int lane = t & 31, w = t >> 5;
    const int g = lane >> 2, tig = lane & 3;
    const int mb2 = (w & 7)*16;

    if (seg == 0){
        // ---- pos head ----
        gemm_big(acc, g_wimg + IMG_POSW1, smem_base, smem_base + SA_U*4, 512, 4);
        epi_big(acc, pos_b1, smu + SB_U);
        __syncthreads();
        {
            float a8[4];
            if (w < 8) gemm_w2_n8(a8, smem_base, smu, 0);
            __syncthreads();
            prefetch_chunk0(smem_base, g_wimg + IMG_ROTW1);
            if (w < 8){
                #pragma unroll
                for (int i = 0; i < 2; i++){
                    int pt = mb2 + g + 8*i;
                    int gi = sidx[pt];
                    #pragma unroll
                    for (int jj = 0; jj < 2; jj++){
                        int col = 2*tig + jj;
                        if (col < 3){
                            float d = a8[i*2+jj] + pos_b2[col];
                            out[(size_t)gi*3 + col] = rays[gi*3 + col] + d;
                        }
                    }
                }
            }
        }
        // ---- rot head ----
        gemm_big(acc, g_wimg + IMG_ROTW1, smem_base, smem_base + SA_U*4, 512, 4);
        epi_big(acc, rot_b1, smu + SB_U);
        __syncthreads();
        {
            float a8[4];
            if (w < 8) gemm_w2_n8(a8, smem_base, smu, 1024);
            __syncthreads();
            prefetch_chunk0(smem_base, g_wimg + IMG_SHSW1);
            if (w < 8){
                #pragma unroll
                for (int i = 0; i < 2; i++){
                    int pt = mb2 + g + 8*i;
                    int gi = sidx[pt];
                    #pragma unroll
                    for (int jj = 0; jj < 2; jj++){
                        int col = 2*tig + jj;
                        if (col < 4){
                            float d = a8[i*2+jj] + rot_b2[col];
                            out[(size_t)3*n + (size_t)gi*4 + col] = rot_emb[(size_t)gi*4 + col] + d;
                        }
                    }
                }
            }
        }
        // ---- shs head ----
        gemm_big(acc, g_wimg + IMG_SHSW1, smem_base, smem_base + SA_U*4, 512, 4);
        epi_big(acc, shs_b1, smu + SB_U);
        __syncthreads();
        if (w < 8){
            float a48[6][4];
            gemm_w2_n48(a48, smem_base, smu, 2048);
            float* o8 = out + (size_t)8*n;
            #pragma unroll
            for (int i = 0; i < 2; i++){
                int pt = mb2 + g + 8*i;
                int gi = sidx[pt];
                const float* se = shs_emb + (size_t)gi*48;
                float* od = o8 + (size_t)gi*48;
                #pragma unroll
                for (int nt = 0; nt < 6; nt++){
                    #pragma unroll
                    for (int jj = 0; jj < 2; jj++){
                        int col = nt*8 + 2*tig + jj;
                        float d = a48[nt][i*2+jj] + shs_b2[col];
                        od[col] = se[col] + d;
                    }
                }
            }
        }
    } else {
        // ---- bgpos head ----
        gemm_big(acc, g_wimg + IMG_BGPOSW1, smem_base, smem_base + SA_U*4, 512, 4);
        epi_big(acc, bgpos_b1, smu + SB_U);
        __syncthreads();
        if (w < 8){
            float a8[4];
            gemm_w2_n8(a8, smem_base, smu, 0);
            #pragma unroll
            for (int i = 0; i < 2; i++){
                int pt = mb2 + g + 8*i;
                int gi = sidx[pt];
                #pragma unroll
                for (int jj = 0; jj < 2; jj++){
                    int col = 2*tig + jj;
                    if (col < 3){
                        float d = a8[i*2+jj] + bgpos_b2[col];
                        out[(size_t)gi*3 + col] = rays[gi*3 + col] + d;
                    }
                }
            }
        }
    }
}

extern "C" void kernel_launch(void* const* d_in, const int* in_sizes, int n_in,
                              void* d_out, int out_size) {
    const float* rays    = (const float*)d_in[0];
    const float* rot_emb = (const float*)d_in[1];
    const float* shs_emb = (const float*)d_in[3];
    const float* tim     = (const float*)d_in[5];
    const float* h_emb   = (const float*)d_in[6];
    const void*  mask    = d_in[7];
    const float* tgt_sp  = (const float*)d_in[8];
    const float* tgt_tp  = (const float*)d_in[9];
    const float* bg_sp   = (const float*)d_in[10];
    const float* bg_tp   = (const float*)d_in[11];
    const float* st_w    = (const float*)d_in[12];
    const float* st_b    = (const float*)d_in[13];
    const float* bg_st_w = (const float*)d_in[14];
    const float* bg_st_b = (const float*)d_in[15];
    const float* pos_w1  = (const float*)d_in[16];
    const float* pos_b1  = (const float*)d_in[17];
    const float* pos_w2  = (const float*)d_in[18];
    const float* pos_b2  = (const float*)d_in[19];
    const float* bgpos_w1= (const float*)d_in[20];
    const float* bgpos_b1= (const float*)d_in[21];
    const float* bgpos_w2= (const float*)d_in[22];
    const float* bgpos_b2= (const float*)d_in[23];
    const float* rot_w1  = (const float*)d_in[24];
    const float* rot_b1  = (const float*)d_in[25];
    const float* rot_w2  = (const float*)d_in[26];
    const float* rot_b2  = (const float*)d_in[27];
    const float* shs_w1  = (const float*)d_in[28];
    const float* shs_b1  = (const float*)d_in[29];
    const float* shs_w2  = (const float*)d_in[30];
    const float* shs_b2  = (const float*)d_in[31];
    float* out = (float*)d_out;
    int n = in_sizes[0] / 3;

    cudaFuncSetAttribute(main_kernel, cudaFuncAttributeMaxDynamicSharedMemorySize, SMEM_BYTES);

    convert_planes<<<(P_TOTAL + 255)/256, 256>>>(tgt_sp, tgt_tp, bg_sp, bg_tp);
    convert_kernel<<<(IMG_TOTAL + 255)/256, 256>>>(
        st_w, bg_st_w, pos_w1, bgpos_w1, rot_w1, shs_w1,
        pos_w2, rot_w2, shs_w2, bgpos_w2);
    setup_kernel<<<1, 256>>>((const unsigned char*)mask);
    elem_kernel<<<(n + 255)/256, 256>>>(rot_emb, shs_emb, tim, h_emb, mask, out, n);
    int nb = (n + 127)/128 + 1;
    main_kernel<<<nb, 512, SMEM_BYTES>>>(
        rays, rot_emb, shs_emb, tim,
        st_b, bg_st_b,
        pos_b1, pos_b2, bgpos_b1, bgpos_b2,
        rot_b1, rot_b2, shs_b1, shs_b2,
        out, n);
}